// round 15
// baseline (speedup 1.0000x reference)
#include <cuda_runtime.h>
#include <cuda_bf16.h>
#include <cuda_fp16.h>
#include <cstdint>

#define D 256
#define NMAX 50000
#define EMAX 300000

// ==================== static device scratch ====================
__device__ float g_wx[(size_t)7 * NMAX * D];
__device__ float g_s[6 * NMAX];
__device__ float g_v[2 * D];
__device__ int   g_cnt[3 * NMAX];
__device__ int   g_off[3 * (NMAX + 1)];
__device__ int   g_cur[3 * NMAX];
__device__ int   g_srcs[3 * EMAX];
__device__ int   g_bsums[3 * 64];
__device__ __nv_bfloat16 g_ha[2 * (size_t)NMAX * D];
__device__ __nv_bfloat16 g_hp[2 * (size_t)NMAX * D];
__device__ __nv_bfloat16 g_wsplit[5 * 2 * D * D];

// ==================== low-level helpers ====================
__device__ __forceinline__ uint32_t smem_to_u32(const void* p) {
    uint32_t a;
    asm("{ .reg .u64 t; cvta.to.shared.u64 t, %1; cvt.u32.u64 %0, t; }" : "=r"(a) : "l"(p));
    return a;
}
__device__ __forceinline__ void cp16(uint32_t saddr, const void* g, bool valid) {
    asm volatile("cp.async.cg.shared.global [%0], [%1], 16, %2;"
                 :: "r"(saddr), "l"(g), "r"(valid ? 16 : 0));
}
__device__ __forceinline__ void cp_commit() { asm volatile("cp.async.commit_group;"); }
__device__ __forceinline__ void ldsm_x4(uint32_t* r, uint32_t addr) {
    asm volatile("ldmatrix.sync.aligned.m8n8.x4.shared.b16 {%0,%1,%2,%3}, [%4];"
                 : "=r"(r[0]), "=r"(r[1]), "=r"(r[2]), "=r"(r[3]) : "r"(addr));
}
__device__ __forceinline__ void mma_bf16(float* c, const uint32_t* a, const uint32_t* b) {
    asm volatile(
        "mma.sync.aligned.m16n8k16.row.col.f32.bf16.bf16.f32 "
        "{%0,%1,%2,%3}, {%4,%5,%6,%7}, {%8,%9}, {%0,%1,%2,%3};"
        : "+f"(c[0]), "+f"(c[1]), "+f"(c[2]), "+f"(c[3])
        : "r"(a[0]), "r"(a[1]), "r"(a[2]), "r"(a[3]), "r"(b[0]), "r"(b[1]));
}

// ==================== split + zero (merged) ====================
struct SplitJob { const float* x; __nv_bfloat16* hi; __nv_bfloat16* lo; int n; };
struct SplitZeroArgs { SplitJob j[7]; int* cnt; float* svec; };

__global__ void split_zero(SplitZeroArgs a) {
    if (blockIdx.y == 7) {
        int total = 6 * NMAX;
        for (int i = blockIdx.x * blockDim.x + threadIdx.x; i < total;
             i += gridDim.x * blockDim.x) {
            if (i < 3 * NMAX) a.cnt[i] = 0;
            a.svec[i] = 0.f;
        }
        return;
    }
    SplitJob jb = a.j[blockIdx.y];
    int n4 = jb.n >> 2;
    for (int i = blockIdx.x * blockDim.x + threadIdx.x; i < n4; i += gridDim.x * blockDim.x) {
        float4 v = ((const float4*)jb.x)[i];
        float vs[4] = {v.x, v.y, v.z, v.w};
        unsigned short hs[4], ls[4];
#pragma unroll
        for (int k = 0; k < 4; k++) {
            __nv_bfloat16 h = __float2bfloat16(vs[k]);
            float r = vs[k] - __bfloat162float(h);
            __nv_bfloat16 l = __float2bfloat16(r);
            hs[k] = *(unsigned short*)&h;
            ls[k] = *(unsigned short*)&l;
        }
        ((uint2*)jb.hi)[i] = make_uint2((uint32_t)hs[0] | ((uint32_t)hs[1] << 16),
                                        (uint32_t)hs[2] | ((uint32_t)hs[3] << 16));
        ((uint2*)jb.lo)[i] = make_uint2((uint32_t)ls[0] | ((uint32_t)ls[1] << 16),
                                        (uint32_t)ls[2] | ((uint32_t)ls[3] << 16));
    }
}

// ==================== CSR build ====================
__global__ void hist3_kernel(const int* e0, const int* e1, const int* e2,
                             int E0, int E1, int E2, int* cnt) {
    int r = blockIdx.y;
    const int* e = r == 0 ? e0 : (r == 1 ? e1 : e2);
    int E = r == 0 ? E0 : (r == 1 ? E1 : E2);
    int i = blockIdx.x * blockDim.x + threadIdx.x;
    if (i < E) atomicAdd(&cnt[r * NMAX + e[E + i]], 1);
}
__global__ void scanA_kernel(const int* cnt, int* off, int* bsums, int n0, int n1, int n2) {
    int r = blockIdx.y;
    int n = r == 0 ? n0 : (r == 1 ? n1 : n2);
    int idx = blockIdx.x * 1024 + threadIdx.x;
    int tid = threadIdx.x, lane = tid & 31, w = tid >> 5;
    __shared__ int wsum[32];
    int v = idx < n ? cnt[r * NMAX + idx] : 0;
    int x = v;
#pragma unroll
    for (int o = 1; o < 32; o <<= 1) {
        int y = __shfl_up_sync(0xffffffffu, x, o);
        if (lane >= o) x += y;
    }
    if (lane == 31) wsum[w] = x;
    __syncthreads();
    if (w == 0) {
        int s = wsum[lane];
#pragma unroll
        for (int o = 1; o < 32; o <<= 1) {
            int y = __shfl_up_sync(0xffffffffu, s, o);
            if (lane >= o) s += y;
        }
        wsum[lane] = s;
    }
    __syncthreads();
    int prefix = w ? wsum[w - 1] : 0;
    int incl = prefix + x;
    if (idx < n) off[r * (NMAX + 1) + idx] = incl - v;
    if (tid == 1023) bsums[r * 64 + blockIdx.x] = incl;
}
// scanB (x<3) + matvec (x=3,4) merged
__global__ void scanB_matvec(int* bsums, int* off, int n0, int n1, int n2,
                             const float* W0, const float* a0,
                             const float* W1, const float* a1, float* v) {
    if (blockIdx.x >= 3) {
        int r = blockIdx.x - 3;
        const float* W = r ? W1 : W0;
        const float* a = r ? a1 : a0;
        int k = threadIdx.x;
        float s0 = 0.f, s1 = 0.f, s2 = 0.f, s3 = 0.f;
#pragma unroll 4
        for (int n = 0; n < D; n += 4) {
            s0 += __ldg(&a[n + 0]) * __ldg(&W[(n + 0) * D + k]);
            s1 += __ldg(&a[n + 1]) * __ldg(&W[(n + 1) * D + k]);
            s2 += __ldg(&a[n + 2]) * __ldg(&W[(n + 2) * D + k]);
            s3 += __ldg(&a[n + 3]) * __ldg(&W[(n + 3) * D + k]);
        }
        v[r * D + k] = (s0 + s1) + (s2 + s3);
        return;
    }
    if (threadIdx.x >= 64) return;
    int r = blockIdx.x;
    int n = r == 0 ? n0 : (r == 1 ? n1 : n2);
    int nb = (n + 1023) >> 10;
    int t = threadIdx.x, lane = t & 31, w = t >> 5;
    __shared__ int sh[2];
    int v2 = t < nb ? bsums[r * 64 + t] : 0;
    int x = v2;
#pragma unroll
    for (int o = 1; o < 32; o <<= 1) {
        int y = __shfl_up_sync(0xffffffffu, x, o);
        if (lane >= o) x += y;
    }
    if (lane == 31) sh[w] = x;
    __syncthreads();
    int incl = x + (w == 1 ? sh[0] : 0);
    if (t < 64) bsums[r * 64 + t] = incl - v2;
    if (t == nb - 1) off[r * (NMAX + 1) + n] = incl;
}
__global__ void scanC_kernel(const int* bsums, int* off, int* cur, int n0, int n1, int n2) {
    int r = blockIdx.y;
    int n = r == 0 ? n0 : (r == 1 ? n1 : n2);
    int idx = blockIdx.x * 1024 + threadIdx.x;
    if (idx < n) {
        int v = off[r * (NMAX + 1) + idx] + bsums[r * 64 + blockIdx.x];
        off[r * (NMAX + 1) + idx] = v;
        cur[r * NMAX + idx] = v;
    }
}
// scatter (y<3) + dotv (y=3,4) merged
__global__ void scatter_dotv(const int* e0, const int* e1, const int* e2,
                             int E0, int E1, int E2, int* cur, int* srcs,
                             const float* hP, const float* hA, const float* v,
                             float* sOut0, float* sOut1, int Np, int Na) {
    int r = blockIdx.y;
    if (r < 3) {
        const int* e = r == 0 ? e0 : (r == 1 ? e1 : e2);
        int E = r == 0 ? E0 : (r == 1 ? E1 : E2);
        int i = blockIdx.x * blockDim.x + threadIdx.x;
        if (i < E) {
            int p = atomicAdd(&cur[r * NMAX + e[E + i]], 1);
            srcs[r * EMAX + p] = e[i];
        }
        return;
    }
    int rr = r - 3;
    const float* x = rr ? hA : hP;
    const float* vv = v + rr * D;
    float* out = rr ? sOut1 : sOut0;
    int n = rr ? Na : Np;
    int idx = blockIdx.x * 8 + (threadIdx.x >> 5);
    if (idx >= n) return;
    int lane = threadIdx.x & 31;
    const float4* row = (const float4*)(x + (size_t)idx * D) + lane * 2;
    const float4* v4 = (const float4*)vv + lane * 2;
    float4 r0 = row[0], r1 = row[1];
    float4 q0 = __ldg(v4), q1 = __ldg(v4 + 1);
    float s = r0.x * q0.x + r0.y * q0.y + r0.z * q0.z + r0.w * q0.w
            + r1.x * q1.x + r1.y * q1.y + r1.z * q1.z + r1.w * q1.w;
#pragma unroll
    for (int o = 16; o; o >>= 1) s += __shfl_xor_sync(0xffffffffu, s, o);
    if (lane == 0) out[idx] = s;
}

// ==================== persistent batched HMMA GEMM: 128x128 tiles, 2 CTA/SM =====
struct GemmJob {
    const __nv_bfloat16 *Ahi, *Alo, *Bhi, *Blo;
    __half* C; const float* bias;
    const float* a1; float* s1;
    const float* a2; float* s2;
    int M; int pad;
};
struct GemmJobs { GemmJob j[5]; int mtiles; int ntiles; };

#define ABYTES (128 * 144)
#define BBYTES (128 * 144)
#define STAGE  (ABYTES + BBYTES)
#define GSM_BYTES (3 * STAGE)

__global__ __launch_bounds__(256, 2) void gemm_batch(GemmJobs jobs) {
    extern __shared__ char smem[];
    uint32_t sb = smem_to_u32(smem);
    int tid = threadIdx.x;
    int wid = tid >> 5, lane = tid & 31;
    int warp_m = wid & 3, warp_n = wid >> 2;
    int tilesPerJob = jobs.mtiles * jobs.ntiles;
    int nTiles = 5 * tilesPerJob;

    for (int t = blockIdx.x; t < nTiles; t += gridDim.x) {
        int job = t / tilesPerJob;
        int rem = t - job * tilesPerJob;
        GemmJob jb = jobs.j[job];
        int m0 = (rem >> 1) * 128;
        int n0 = (rem & 1) * 128;
        if (m0 >= jb.M) continue;

        float acc[2][8][4];
#pragma unroll
        for (int i = 0; i < 2; i++)
#pragma unroll
            for (int n = 0; n < 8; n++)
#pragma unroll
                for (int k = 0; k < 4; k++) acc[i][n][k] = 0.f;

        const __nv_bfloat16* Aseg[3] = {jb.Ahi, jb.Alo, jb.Ahi};
        const __nv_bfloat16* Bseg[3] = {jb.Bhi, jb.Bhi, jb.Blo};

#define ISSUE_LOAD(c, buf) do {                                                 \
        int seg_ = (c) >> 2, k0_ = ((c) & 3) * 64;                              \
        const __nv_bfloat16* Ag_ = Aseg[seg_];                                  \
        const __nv_bfloat16* Bg_ = Bseg[seg_];                                  \
        uint32_t sA_ = sb + (uint32_t)(buf) * STAGE;                            \
        uint32_t sB_ = sA_ + ABYTES;                                            \
        _Pragma("unroll")                                                       \
        for (int i_ = 0; i_ < 4; i_++) {                                        \
            int idx_ = tid + i_ * 256;                                          \
            int r_ = idx_ >> 3, c_ = idx_ & 7;                                  \
            int gm_ = m0 + r_;                                                  \
            bool v_ = gm_ < jb.M;                                               \
            int gmc_ = v_ ? gm_ : (jb.M - 1);                                   \
            cp16(sA_ + r_ * 144 + c_ * 16,                                      \
                 Ag_ + (size_t)gmc_ * 256 + k0_ + c_ * 8, v_);                  \
        }                                                                       \
        _Pragma("unroll")                                                       \
        for (int i_ = 0; i_ < 4; i_++) {                                        \
            int idx_ = tid + i_ * 256;                                          \
            int r_ = idx_ >> 3, c_ = idx_ & 7;                                  \
            cp16(sB_ + r_ * 144 + c_ * 16,                                      \
                 Bg_ + (size_t)(n0 + r_) * 256 + k0_ + c_ * 8, true);           \
        }                                                                       \
        cp_commit();                                                            \
    } while (0)

        ISSUE_LOAD(0, 0);
        ISSUE_LOAD(1, 1);
#pragma unroll 1
        for (int c = 0; c < 12; c++) {
            if (c < 11) asm volatile("cp.async.wait_group 1;");
            else        asm volatile("cp.async.wait_group 0;");
            __syncthreads();
            if (c + 2 < 12) ISSUE_LOAD(c + 2, (c + 2) % 3);
            uint32_t sA = sb + (uint32_t)(c % 3) * STAGE;
            uint32_t sB = sA + ABYTES;
#pragma unroll
            for (int k16 = 0; k16 < 4; k16++) {
                uint32_t a[2][4];
#pragma unroll
                for (int i = 0; i < 2; i++) {
                    uint32_t row = warp_m * 32 + i * 16 + (lane & 15);
                    ldsm_x4(a[i], sA + row * 144 + k16 * 32 + ((lane >> 4) * 16));
                }
                uint32_t b[8][2];
#pragma unroll
                for (int j = 0; j < 4; j++) {
                    uint32_t row = warp_n * 64 + j * 16 + (lane & 7) + (((lane >> 4) & 1) << 3);
                    uint32_t tt[4];
                    ldsm_x4(tt, sB + row * 144 + k16 * 32 + (((lane >> 3) & 1) << 4));
                    b[2 * j][0] = tt[0]; b[2 * j][1] = tt[1];
                    b[2 * j + 1][0] = tt[2]; b[2 * j + 1][1] = tt[3];
                }
#pragma unroll
                for (int i = 0; i < 2; i++)
#pragma unroll
                    for (int n = 0; n < 8; n++) mma_bf16(acc[i][n], a[i], b[n]);
            }
        }
        __syncthreads();

        // ---- epilogue: fp16 C stores + fused fp32 dot partials ----
        bool need_dots = (jb.a1 != nullptr) || (jb.a2 != nullptr);
        float* sdot = (float*)smem;
        if (need_dots) {
            if (tid < 256) sdot[tid] = 0.f;
            __syncthreads();
        }

#pragma unroll
        for (int i = 0; i < 2; i++) {
            int rloc = warp_m * 32 + i * 16 + (lane >> 2);
            int rowA = m0 + rloc;
            int rowB = rowA + 8;
            float d1a = 0.f, d1b = 0.f, d2a = 0.f, d2b = 0.f;
#pragma unroll
            for (int n = 0; n < 8; n++) {
                int col = n0 + warp_n * 64 + n * 8 + 2 * (lane & 3);
                float b0 = 0.f, b1 = 0.f;
                if (jb.bias) { b0 = __ldg(jb.bias + col); b1 = __ldg(jb.bias + col + 1); }
                float c0 = acc[i][n][0] + b0, c1 = acc[i][n][1] + b1;
                float c2 = acc[i][n][2] + b0, c3 = acc[i][n][3] + b1;
                __half2* base = (__half2*)jb.C;
                if (rowA < jb.M) base[((size_t)rowA * 256 + col) >> 1] = __floats2half2_rn(c0, c1);
                if (rowB < jb.M) base[((size_t)rowB * 256 + col) >> 1] = __floats2half2_rn(c2, c3);
                if (jb.a1) {
                    float q0 = __ldg(jb.a1 + col), q1 = __ldg(jb.a1 + col + 1);
                    d1a += c0 * q0 + c1 * q1;
                    d1b += c2 * q0 + c3 * q1;
                }
                if (jb.a2) {
                    float q0 = __ldg(jb.a2 + col), q1 = __ldg(jb.a2 + col + 1);
                    d2a += c0 * q0 + c1 * q1;
                    d2b += c2 * q0 + c3 * q1;
                }
            }
            if (jb.a1) {
                d1a += __shfl_xor_sync(0xffffffffu, d1a, 1);
                d1a += __shfl_xor_sync(0xffffffffu, d1a, 2);
                d1b += __shfl_xor_sync(0xffffffffu, d1b, 1);
                d1b += __shfl_xor_sync(0xffffffffu, d1b, 2);
                if ((lane & 3) == 0) {
                    atomicAdd(&sdot[rloc], d1a);
                    atomicAdd(&sdot[rloc + 8], d1b);
                }
            }
            if (jb.a2) {
                d2a += __shfl_xor_sync(0xffffffffu, d2a, 1);
                d2a += __shfl_xor_sync(0xffffffffu, d2a, 2);
                d2b += __shfl_xor_sync(0xffffffffu, d2b, 1);
                d2b += __shfl_xor_sync(0xffffffffu, d2b, 2);
                if ((lane & 3) == 0) {
                    atomicAdd(&sdot[128 + rloc], d2a);
                    atomicAdd(&sdot[128 + rloc + 8], d2b);
                }
            }
        }
        if (need_dots) {
            __syncthreads();
            if (tid < 128 && m0 + tid < jb.M) {
                if (jb.s1) atomicAdd(&jb.s1[m0 + tid], sdot[tid]);
                if (jb.s2) atomicAdd(&jb.s2[m0 + tid], sdot[128 + tid]);
            }
        }
        __syncthreads();   // protect smem (sdot aliases buffer 0) before next tile's loads
    }
}

// ==================== warp-level softmax-aggregation (fp16 gather) ====================
__device__ __forceinline__ void warp_rel_agg(
    const int* __restrict__ srcs, int e0, int deg, float sd,
    const float* __restrict__ s_src, const __half* __restrict__ wx,
    int lane, float4& acc0, float4& acc1) {
    acc0 = make_float4(0.f, 0.f, 0.f, 0.f);
    acc1 = make_float4(0.f, 0.f, 0.f, 0.f);
    if (deg <= 0) return;
    float m = -1e30f;
    for (int base = 0; base < deg; base += 32) {
        int e = base + lane;
        float sc = -1e30f;
        if (e < deg) {
            float x = s_src[srcs[e0 + e]] + sd;
            sc = x > 0.f ? x : 0.2f * x;
        }
#pragma unroll
        for (int o = 16; o; o >>= 1) sc = fmaxf(sc, __shfl_xor_sync(0xffffffffu, sc, o));
        m = fmaxf(m, sc);
    }
    float ssum = 0.f;
    for (int base = 0; base < deg; base += 32) {
        int e = base + lane;
        int s = 0; float wgt = 0.f;
        if (e < deg) {
            s = srcs[e0 + e];
            float x = s_src[s] + sd;
            x = x > 0.f ? x : 0.2f * x;
            wgt = expf(x - m);
        }
        float part = wgt;
#pragma unroll
        for (int o = 16; o; o >>= 1) part += __shfl_xor_sync(0xffffffffu, part, o);
        ssum += part;
        int cnt = min(32, deg - base);
        int j = 0;
        for (; j + 2 <= cnt; j += 2) {
            float wj0 = __shfl_sync(0xffffffffu, wgt, j);
            float wj1 = __shfl_sync(0xffffffffu, wgt, j + 1);
            int sj0 = __shfl_sync(0xffffffffu, s, j);
            int sj1 = __shfl_sync(0xffffffffu, s, j + 1);
            uint4 p0 = *((const uint4*)(wx + (size_t)sj0 * D) + lane);
            uint4 p1 = *((const uint4*)(wx + (size_t)sj1 * D) + lane);
            float2 f;
            f = __half22float2(*(__half2*)&p0.x); acc0.x += wj0 * f.x; acc0.y += wj0 * f.y;
            f = __half22float2(*(__half2*)&p0.y); acc0.z += wj0 * f.x; acc0.w += wj0 * f.y;
            f = __half22float2(*(__half2*)&p0.z); acc1.x += wj0 * f.x; acc1.y += wj0 * f.y;
            f = __half22float2(*(__half2*)&p0.w); acc1.z += wj0 * f.x; acc1.w += wj0 * f.y;
            f = __half22float2(*(__half2*)&p1.x); acc0.x += wj1 * f.x; acc0.y += wj1 * f.y;
            f = __half22float2(*(__half2*)&p1.y); acc0.z += wj1 * f.x; acc0.w += wj1 * f.y;
            f = __half22float2(*(__half2*)&p1.z); acc1.x += wj1 * f.x; acc1.y += wj1 * f.y;
            f = __half22float2(*(__half2*)&p1.w); acc1.z += wj1 * f.x; acc1.w += wj1 * f.y;
        }
        if (j < cnt) {
            float wj = __shfl_sync(0xffffffffu, wgt, j);
            int sj = __shfl_sync(0xffffffffu, s, j);
            uint4 p = *((const uint4*)(wx + (size_t)sj * D) + lane);
            float2 f;
            f = __half22float2(*(__half2*)&p.x); acc0.x += wj * f.x; acc0.y += wj * f.y;
            f = __half22float2(*(__half2*)&p.y); acc0.z += wj * f.x; acc0.w += wj * f.y;
            f = __half22float2(*(__half2*)&p.z); acc1.x += wj * f.x; acc1.y += wj * f.y;
            f = __half22float2(*(__half2*)&p.w); acc1.z += wj * f.x; acc1.w += wj * f.y;
        }
    }
    float inv = 1.f / ssum;
    acc0.x *= inv; acc0.y *= inv; acc0.z *= inv; acc0.w *= inv;
    acc1.x *= inv; acc1.y *= inv; acc1.z *= inv; acc1.w *= inv;
}

__device__ __forceinline__ void load_half8(const __half* p, int b, int lane,
                                           float4& f0, float4& f1) {
    uint4 u = *((const uint4*)(p + (size_t)b * D) + lane);
    float2 t;
    t = __half22float2(*(__half2*)&u.x); f0.x = t.x; f0.y = t.y;
    t = __half22float2(*(__half2*)&u.y); f0.z = t.x; f0.w = t.y;
    t = __half22float2(*(__half2*)&u.z); f1.x = t.x; f1.y = t.y;
    t = __half22float2(*(__half2*)&u.w); f1.z = t.x; f1.w = t.y;
}

// ==================== combined aggregation -> output ====================
struct AggArgs {
    const int *srcs0, *off0; const float *ssrc0, *sdst0; const __half* wx0;
    const int *srcs1, *off1; const float *ssrc1, *sdst1; const __half* wx1;
    const int *srcs2, *off2; const float *ssrc2, *sdst2; const __half* wx2;
    const __half *selfa, *selfp; const float* q;
    float* out; int Na, Np, nblocksA;
};

__global__ void agg_all(AggArgs a) {
    int w = threadIdx.x >> 5, lane = threadIdx.x & 31;
    if (blockIdx.x < (unsigned)a.nblocksA) {
        int b = blockIdx.x * 8 + w;
        if (b >= a.Na) return;
        int e0 = a.off1[b];
        int deg = a.off1[b + 1] - e0;
        float4 x0, x1;
        warp_rel_agg(a.srcs1, e0, deg, deg > 0 ? a.sdst1[b] : 0.f, a.ssrc1, a.wx1, lane, x0, x1);
        float4 s0, s1;
        load_half8(a.selfa, b, lane, s0, s1);
        float v;
        v = s0.x + x0.x; x0.x = v > 0.f ? v : expm1f(v);
        v = s0.y + x0.y; x0.y = v > 0.f ? v : expm1f(v);
        v = s0.z + x0.z; x0.z = v > 0.f ? v : expm1f(v);
        v = s0.w + x0.w; x0.w = v > 0.f ? v : expm1f(v);
        v = s1.x + x1.x; x1.x = v > 0.f ? v : expm1f(v);
        v = s1.y + x1.y; x1.y = v > 0.f ? v : expm1f(v);
        v = s1.z + x1.z; x1.z = v > 0.f ? v : expm1f(v);
        v = s1.w + x1.w; x1.w = v > 0.f ? v : expm1f(v);
        float4* o = (float4*)(a.out + (size_t)b * D) + lane * 2;
        o[0] = x0; o[1] = x1;
    } else {
        int b = (blockIdx.x - a.nblocksA) * 8 + w;
        if (b >= a.Np) return;
        int e0a = a.off0[b];
        int dega = a.off0[b + 1] - e0a;
        float4 x0, x1;
        warp_rel_agg(a.srcs0, e0a, dega, dega > 0 ? a.sdst0[b] : 0.f, a.ssrc0, a.wx0, lane, x0, x1);
        int e0c = a.off2[b];
        int degc = a.off2[b + 1] - e0c;
        float4 c0, c1;
        warp_rel_agg(a.srcs2, e0c, degc, degc > 0 ? a.sdst2[b] : 0.f, a.ssrc2, a.wx2, lane, c0, c1);

        const float4* q4 = (const float4*)a.q + lane * 2;
        float4 q0 = __ldg(q4), q1 = __ldg(q4 + 1);
        float t1 = tanhf(x0.x) * q0.x + tanhf(x0.y) * q0.y + tanhf(x0.z) * q0.z + tanhf(x0.w) * q0.w
                 + tanhf(x1.x) * q1.x + tanhf(x1.y) * q1.y + tanhf(x1.z) * q1.z + tanhf(x1.w) * q1.w;
        float t2 = tanhf(c0.x) * q0.x + tanhf(c0.y) * q0.y + tanhf(c0.z) * q0.z + tanhf(c0.w) * q0.w
                 + tanhf(c1.x) * q1.x + tanhf(c1.y) * q1.y + tanhf(c1.z) * q1.z + tanhf(c1.w) * q1.w;
#pragma unroll
        for (int o = 16; o; o >>= 1) {
            t1 += __shfl_xor_sync(0xffffffffu, t1, o);
            t2 += __shfl_xor_sync(0xffffffffu, t2, o);
        }
        float mm = fmaxf(t1, t2);
        float w1 = expf(t1 - mm), w2 = expf(t2 - mm);
        float z = 1.f / (w1 + w2);
        w1 *= z; w2 *= z;
        float4 s0, s1;
        load_half8(a.selfp, b, lane, s0, s1);
        float v;
        v = s0.x + w1 * x0.x + w2 * c0.x; s0.x = v > 0.f ? v : expm1f(v);
        v = s0.y + w1 * x0.y + w2 * c0.y; s0.y = v > 0.f ? v : expm1f(v);
        v = s0.z + w1 * x0.z + w2 * c0.z; s0.z = v > 0.f ? v : expm1f(v);
        v = s0.w + w1 * x0.w + w2 * c0.w; s0.w = v > 0.f ? v : expm1f(v);
        v = s1.x + w1 * x1.x + w2 * c1.x; s1.x = v > 0.f ? v : expm1f(v);
        v = s1.y + w1 * x1.y + w2 * c1.y; s1.y = v > 0.f ? v : expm1f(v);
        v = s1.z + w1 * x1.z + w2 * c1.z; s1.z = v > 0.f ? v : expm1f(v);
        v = s1.w + w1 * x1.w + w2 * c1.w; s1.w = v > 0.f ? v : expm1f(v);
        float4* o = (float4*)(a.out + (size_t)(a.Na + b) * D) + lane * 2;
        o[0] = s0; o[1] = s1;
    }
}

// ==================== host launch ====================
extern "C" void kernel_launch(void* const* d_in, const int* in_sizes, int n_in,
                              void* d_out, int out_size) {
    const float* h_author = (const float*)d_in[0];
    const float* h_paper  = (const float*)d_in[1];
    const int* ei_ap = (const int*)d_in[2];
    const int* ei_pa = (const int*)d_in[3];
    const int* ei_pp = (const int*)d_in[4];
    const float* W_ap = (const float*)d_in[5];
    const float* a_src_ap = (const float*)d_in[6];
    const float* a_dst_ap = (const float*)d_in[7];
    const float* W_pa = (const float*)d_in[8];
    const float* a_src_pa = (const float*)d_in[9];
    const float* a_dst_pa = (const float*)d_in[10];
    const float* W_pp = (const float*)d_in[11];
    const float* a_src_pp = (const float*)d_in[12];
    const float* a_dst_pp = (const float*)d_in[13];
    const float* Wself_a = (const float*)d_in[14];
    const float* bself_a = (const float*)d_in[15];
    const float* Wself_p = (const float*)d_in[16];
    const float* bself_p = (const float*)d_in[17];
    const float* q_paper  = (const float*)d_in[19];

    int Na = in_sizes[0] / D;
    int Np = in_sizes[1] / D;
    int Eap = in_sizes[2] / 2;
    int Epa = in_sizes[3] / 2;
    int Epp = in_sizes[4] / 2;

    float *wx, *svec, *vv;
    int *cnt, *off, *cur, *srcs, *bsums;
    __nv_bfloat16 *ha, *hp, *wsp;
    cudaGetSymbolAddress((void**)&wx, g_wx);
    cudaGetSymbolAddress((void**)&svec, g_s);
    cudaGetSymbolAddress((void**)&vv, g_v);
    cudaGetSymbolAddress((void**)&cnt, g_cnt);
    cudaGetSymbolAddress((void**)&off, g_off);
    cudaGetSymbolAddress((void**)&cur, g_cur);
    cudaGetSymbolAddress((void**)&srcs, g_srcs);
    cudaGetSymbolAddress((void**)&bsums, g_bsums);
    cudaGetSymbolAddress((void**)&ha, g_ha);
    cudaGetSymbolAddress((void**)&hp, g_hp);
    cudaGetSymbolAddress((void**)&wsp, g_wsplit);

    const size_t WXS = (size_t)NMAX * D;
    float* wxp[7];
    for (int i = 0; i < 7; i++) wxp[i] = wx + i * WXS;
    __half* hx0 = (__half*)wxp[0];
    __half* hx1 = (__half*)wxp[2];
    __half* hx2 = (__half*)wxp[4];
    __half* hselfA = (__half*)wxp[5];
    __half* hselfP = (__half*)wxp[6];
    float* sp[6];
    for (int i = 0; i < 6; i++) sp[i] = svec + (size_t)i * NMAX;
    __nv_bfloat16* haHi = ha;            __nv_bfloat16* haLo = ha + WXS;
    __nv_bfloat16* hpHi = hp;            __nv_bfloat16* hpLo = hp + WXS;
    __nv_bfloat16* wHi[5]; __nv_bfloat16* wLo[5];
    for (int i = 0; i < 5; i++) { wHi[i] = wsp + (size_t)(2 * i) * D * D; wLo[i] = wHi[i] + D * D; }

    // (1) split + zero
    SplitZeroArgs sz;
    sz.j[0] = {h_author, haHi, haLo, Na * D};
    sz.j[1] = {h_paper,  hpHi, hpLo, Np * D};
    sz.j[2] = {W_ap,    wHi[0], wLo[0], D * D};
    sz.j[3] = {W_pa,    wHi[1], wLo[1], D * D};
    sz.j[4] = {W_pp,    wHi[2], wLo[2], D * D};
    sz.j[5] = {Wself_a, wHi[3], wLo[3], D * D};
    sz.j[6] = {Wself_p, wHi[4], wLo[4], D * D};
    sz.cnt = cnt; sz.svec = svec;
    split_zero<<<dim3(148, 8), 256>>>(sz);

    // (2) histogram   (3) scanA
    int Emax3 = max(Eap, max(Epa, Epp));
    hist3_kernel<<<dim3((Emax3 + 255) / 256, 3), 256>>>(ei_ap, ei_pa, ei_pp, Eap, Epa, Epp, cnt);
    scanA_kernel<<<dim3(49, 3), 1024>>>(cnt, off, bsums, Np, Na, Np);

    // (4) persistent batched HMMA GEMMs  [4th launch -> ncu window]
    GemmJobs gj;
    gj.j[0] = {haHi, haLo, wHi[0], wLo[0], hx0, nullptr, a_src_ap, sp[0], nullptr, nullptr, Na, 0};
    gj.j[1] = {hpHi, hpLo, wHi[1], wLo[1], hx1, nullptr, a_src_pa, sp[2], nullptr, nullptr, Np, 0};
    gj.j[2] = {hpHi, hpLo, wHi[2], wLo[2], hx2, nullptr, a_src_pp, sp[4], a_dst_pp, sp[5], Np, 0};
    gj.j[3] = {haHi, haLo, wHi[3], wLo[3], hselfA, bself_a, nullptr, nullptr, nullptr, nullptr, Na, 0};
    gj.j[4] = {hpHi, hpLo, wHi[4], wLo[4], hselfP, bself_p, nullptr, nullptr, nullptr, nullptr, Np, 0};
    int maxM = max(Na, Np);
    gj.mtiles = (maxM + 127) / 128;
    gj.ntiles = 2;
    int smCount = 148;
    cudaDeviceGetAttribute(&smCount, cudaDevAttrMultiProcessorCount, 0);
    int nTiles = 5 * gj.mtiles * gj.ntiles;
    int pgrid = min(2 * smCount, nTiles);
    cudaFuncSetAttribute(gemm_batch, cudaFuncAttributeMaxDynamicSharedMemorySize, GSM_BYTES);
    gemm_batch<<<pgrid, 256, GSM_BYTES>>>(gj);

    // (5) scanB + matvec (merged)   (6) scanC
    scanB_matvec<<<5, 256>>>(bsums, off, Np, Na, Np, W_ap, a_dst_ap, W_pa, a_dst_pa, vv);
    scanC_kernel<<<dim3(49, 3), 1024>>>(bsums, off, cur, Np, Na, Np);

    // (7) scatter + dotv (merged)
    int sx = max((Emax3 + 255) / 256, (maxM + 7) / 8);
    scatter_dotv<<<dim3(sx, 5), 256>>>(ei_ap, ei_pa, ei_pp, Eap, Epa, Epp, cur, srcs,
                                       h_paper, h_author, vv, sp[1], sp[3], Np, Na);

    // (8) combined aggregation -> output
    float* out = (float*)d_out;
    AggArgs aa;
    aa.srcs0 = srcs + 0 * EMAX; aa.off0 = off + 0 * (NMAX + 1);
    aa.ssrc0 = sp[0]; aa.sdst0 = sp[1]; aa.wx0 = hx0;
    aa.srcs1 = srcs + 1 * EMAX; aa.off1 = off + 1 * (NMAX + 1);
    aa.ssrc1 = sp[2]; aa.sdst1 = sp[3]; aa.wx1 = hx1;
    aa.srcs2 = srcs + 2 * EMAX; aa.off2 = off + 2 * (NMAX + 1);
    aa.ssrc2 = sp[4]; aa.sdst2 = sp[5]; aa.wx2 = hx2;
    aa.selfa = hselfA; aa.selfp = hselfP; aa.q = q_paper;
    aa.out = out; aa.Na = Na; aa.Np = Np;
    aa.nblocksA = (Na + 7) / 8;
    int nblocksP = (Np + 7) / 8;
    agg_all<<<aa.nblocksA + nblocksP, 256>>>(aa);
}

// round 16
// speedup vs baseline: 1.0213x; 1.0213x over previous
#include <cuda_runtime.h>
#include <cuda_bf16.h>
#include <cuda_fp16.h>
#include <cstdint>

#define D 256
#define NMAX 50000
#define EMAX 300000

// ==================== static device scratch ====================
// slots 0,2,4 = fp16 gather sources (ap,pa,pp); slots 5,6 = fp16 self transforms
__device__ float g_wx[(size_t)7 * NMAX * D];
__device__ float g_s[6 * NMAX];
__device__ float g_v[2 * D];
__device__ int   g_cnt[3 * NMAX];
__device__ int   g_off[3 * (NMAX + 1)];
__device__ int   g_cur[3 * NMAX];
__device__ int   g_srcs[3 * EMAX];
__device__ int   g_bsums[3 * 64];
__device__ __nv_bfloat16 g_ha[2 * (size_t)NMAX * D];
__device__ __nv_bfloat16 g_hp[2 * (size_t)NMAX * D];
__device__ __nv_bfloat16 g_wsplit[5 * 2 * D * D];

// ==================== low-level helpers ====================
__device__ __forceinline__ uint32_t smem_to_u32(const void* p) {
    uint32_t a;
    asm("{ .reg .u64 t; cvta.to.shared.u64 t, %1; cvt.u32.u64 %0, t; }" : "=r"(a) : "l"(p));
    return a;
}
__device__ __forceinline__ void cp16(uint32_t saddr, const void* g, bool valid) {
    asm volatile("cp.async.cg.shared.global [%0], [%1], 16, %2;"
                 :: "r"(saddr), "l"(g), "r"(valid ? 16 : 0));
}
__device__ __forceinline__ void cp_commit() { asm volatile("cp.async.commit_group;"); }
__device__ __forceinline__ void ldsm_x4(uint32_t* r, uint32_t addr) {
    asm volatile("ldmatrix.sync.aligned.m8n8.x4.shared.b16 {%0,%1,%2,%3}, [%4];"
                 : "=r"(r[0]), "=r"(r[1]), "=r"(r[2]), "=r"(r[3]) : "r"(addr));
}
__device__ __forceinline__ void mma_bf16(float* c, const uint32_t* a, const uint32_t* b) {
    asm volatile(
        "mma.sync.aligned.m16n8k16.row.col.f32.bf16.bf16.f32 "
        "{%0,%1,%2,%3}, {%4,%5,%6,%7}, {%8,%9}, {%0,%1,%2,%3};"
        : "+f"(c[0]), "+f"(c[1]), "+f"(c[2]), "+f"(c[3])
        : "r"(a[0]), "r"(a[1]), "r"(a[2]), "r"(a[3]), "r"(b[0]), "r"(b[1]));
}

// ==================== split + zero (merged) ====================
struct SplitJob { const float* x; __nv_bfloat16* hi; __nv_bfloat16* lo; int n; };
struct SplitZeroArgs { SplitJob j[7]; int* cnt; float* svec; };

__global__ void split_zero(SplitZeroArgs a) {
    if (blockIdx.y == 7) {
        int total = 6 * NMAX;
        for (int i = blockIdx.x * blockDim.x + threadIdx.x; i < total;
             i += gridDim.x * blockDim.x) {
            if (i < 3 * NMAX) a.cnt[i] = 0;
            a.svec[i] = 0.f;
        }
        return;
    }
    SplitJob jb = a.j[blockIdx.y];
    int n4 = jb.n >> 2;
    for (int i = blockIdx.x * blockDim.x + threadIdx.x; i < n4; i += gridDim.x * blockDim.x) {
        float4 v = ((const float4*)jb.x)[i];
        float vs[4] = {v.x, v.y, v.z, v.w};
        unsigned short hs[4], ls[4];
#pragma unroll
        for (int k = 0; k < 4; k++) {
            __nv_bfloat16 h = __float2bfloat16(vs[k]);
            float r = vs[k] - __bfloat162float(h);
            __nv_bfloat16 l = __float2bfloat16(r);
            hs[k] = *(unsigned short*)&h;
            ls[k] = *(unsigned short*)&l;
        }
        ((uint2*)jb.hi)[i] = make_uint2((uint32_t)hs[0] | ((uint32_t)hs[1] << 16),
                                        (uint32_t)hs[2] | ((uint32_t)hs[3] << 16));
        ((uint2*)jb.lo)[i] = make_uint2((uint32_t)ls[0] | ((uint32_t)ls[1] << 16),
                                        (uint32_t)ls[2] | ((uint32_t)ls[3] << 16));
    }
}

// ==================== CSR build ====================
__global__ void hist3_kernel(const int* e0, const int* e1, const int* e2,
                             int E0, int E1, int E2, int* cnt) {
    int r = blockIdx.y;
    const int* e = r == 0 ? e0 : (r == 1 ? e1 : e2);
    int E = r == 0 ? E0 : (r == 1 ? E1 : E2);
    int i = blockIdx.x * blockDim.x + threadIdx.x;
    if (i < E) atomicAdd(&cnt[r * NMAX + e[E + i]], 1);
}
__global__ void scanA_kernel(const int* cnt, int* off, int* bsums, int n0, int n1, int n2) {
    int r = blockIdx.y;
    int n = r == 0 ? n0 : (r == 1 ? n1 : n2);
    int idx = blockIdx.x * 1024 + threadIdx.x;
    int tid = threadIdx.x, lane = tid & 31, w = tid >> 5;
    __shared__ int wsum[32];
    int v = idx < n ? cnt[r * NMAX + idx] : 0;
    int x = v;
#pragma unroll
    for (int o = 1; o < 32; o <<= 1) {
        int y = __shfl_up_sync(0xffffffffu, x, o);
        if (lane >= o) x += y;
    }
    if (lane == 31) wsum[w] = x;
    __syncthreads();
    if (w == 0) {
        int s = wsum[lane];
#pragma unroll
        for (int o = 1; o < 32; o <<= 1) {
            int y = __shfl_up_sync(0xffffffffu, s, o);
            if (lane >= o) s += y;
        }
        wsum[lane] = s;
    }
    __syncthreads();
    int prefix = w ? wsum[w - 1] : 0;
    int incl = prefix + x;
    if (idx < n) off[r * (NMAX + 1) + idx] = incl - v;
    if (tid == 1023) bsums[r * 64 + blockIdx.x] = incl;
}
// scanB (x<3) + matvec (x=3,4) merged
__global__ void scanB_matvec(int* bsums, int* off, int n0, int n1, int n2,
                             const float* W0, const float* a0,
                             const float* W1, const float* a1, float* v) {
    if (blockIdx.x >= 3) {
        int r = blockIdx.x - 3;
        const float* W = r ? W1 : W0;
        const float* a = r ? a1 : a0;
        int k = threadIdx.x;
        float s0 = 0.f, s1 = 0.f, s2 = 0.f, s3 = 0.f;
#pragma unroll 4
        for (int n = 0; n < D; n += 4) {
            s0 += __ldg(&a[n + 0]) * __ldg(&W[(n + 0) * D + k]);
            s1 += __ldg(&a[n + 1]) * __ldg(&W[(n + 1) * D + k]);
            s2 += __ldg(&a[n + 2]) * __ldg(&W[(n + 2) * D + k]);
            s3 += __ldg(&a[n + 3]) * __ldg(&W[(n + 3) * D + k]);
        }
        v[r * D + k] = (s0 + s1) + (s2 + s3);
        return;
    }
    if (threadIdx.x >= 64) return;
    int r = blockIdx.x;
    int n = r == 0 ? n0 : (r == 1 ? n1 : n2);
    int nb = (n + 1023) >> 10;
    int t = threadIdx.x, lane = t & 31, w = t >> 5;
    __shared__ int sh[2];
    int v2 = t < nb ? bsums[r * 64 + t] : 0;
    int x = v2;
#pragma unroll
    for (int o = 1; o < 32; o <<= 1) {
        int y = __shfl_up_sync(0xffffffffu, x, o);
        if (lane >= o) x += y;
    }
    if (lane == 31) sh[w] = x;
    __syncthreads();
    int incl = x + (w == 1 ? sh[0] : 0);
    if (t < 64) bsums[r * 64 + t] = incl - v2;
    if (t == nb - 1) off[r * (NMAX + 1) + n] = incl;
}
__global__ void scanC_kernel(const int* bsums, int* off, int* cur, int n0, int n1, int n2) {
    int r = blockIdx.y;
    int n = r == 0 ? n0 : (r == 1 ? n1 : n2);
    int idx = blockIdx.x * 1024 + threadIdx.x;
    if (idx < n) {
        int v = off[r * (NMAX + 1) + idx] + bsums[r * 64 + blockIdx.x];
        off[r * (NMAX + 1) + idx] = v;
        cur[r * NMAX + idx] = v;
    }
}
// scatter (y<3) + dotv (y=3,4) merged
__global__ void scatter_dotv(const int* e0, const int* e1, const int* e2,
                             int E0, int E1, int E2, int* cur, int* srcs,
                             const float* hP, const float* hA, const float* v,
                             float* sOut0, float* sOut1, int Np, int Na) {
    int r = blockIdx.y;
    if (r < 3) {
        const int* e = r == 0 ? e0 : (r == 1 ? e1 : e2);
        int E = r == 0 ? E0 : (r == 1 ? E1 : E2);
        int i = blockIdx.x * blockDim.x + threadIdx.x;
        if (i < E) {
            int p = atomicAdd(&cur[r * NMAX + e[E + i]], 1);
            srcs[r * EMAX + p] = e[i];
        }
        return;
    }
    int rr = r - 3;
    const float* x = rr ? hA : hP;
    const float* vv = v + rr * D;
    float* out = rr ? sOut1 : sOut0;
    int n = rr ? Na : Np;
    int idx = blockIdx.x * 8 + (threadIdx.x >> 5);
    if (idx >= n) return;
    int lane = threadIdx.x & 31;
    const float4* row = (const float4*)(x + (size_t)idx * D) + lane * 2;
    const float4* v4 = (const float4*)vv + lane * 2;
    float4 r0 = row[0], r1 = row[1];
    float4 q0 = __ldg(v4), q1 = __ldg(v4 + 1);
    float s = r0.x * q0.x + r0.y * q0.y + r0.z * q0.z + r0.w * q0.w
            + r1.x * q1.x + r1.y * q1.y + r1.z * q1.z + r1.w * q1.w;
#pragma unroll
    for (int o = 16; o; o >>= 1) s += __shfl_xor_sync(0xffffffffu, s, o);
    if (lane == 0) out[idx] = s;
}

// ==================== batched HMMA GEMM: 128x128 tiles, 2 CTA/SM ====================
struct GemmJob {
    const __nv_bfloat16 *Ahi, *Alo, *Bhi, *Blo;
    __half* C; const float* bias;
    const float* a1; float* s1;
    const float* a2; float* s2;
    int M; int pad;
};
struct GemmJobs { GemmJob j[5]; };

#define ABYTES (128 * 144)
#define BBYTES (128 * 144)
#define STAGE  (ABYTES + BBYTES)
#define GSM_BYTES (3 * STAGE)

__global__ __launch_bounds__(256, 2) void gemm_batch(GemmJobs jobs) {
    extern __shared__ char smem[];
    GemmJob jb = jobs.j[blockIdx.z];
    int m0 = blockIdx.x * 128;
    if (m0 >= jb.M) return;
    int n0 = blockIdx.y * 128;
    uint32_t sb = smem_to_u32(smem);
    int tid = threadIdx.x;
    int wid = tid >> 5, lane = tid & 31;
    int warp_m = wid & 3, warp_n = wid >> 2;

    float acc[2][8][4];
#pragma unroll
    for (int i = 0; i < 2; i++)
#pragma unroll
        for (int n = 0; n < 8; n++)
#pragma unroll
            for (int k = 0; k < 4; k++) acc[i][n][k] = 0.f;

    const __nv_bfloat16* Aseg[3] = {jb.Ahi, jb.Alo, jb.Ahi};
    const __nv_bfloat16* Bseg[3] = {jb.Bhi, jb.Bhi, jb.Blo};

#define ISSUE_LOAD(c, buf) do {                                                 \
        int seg_ = (c) >> 2, k0_ = ((c) & 3) * 64;                              \
        const __nv_bfloat16* Ag_ = Aseg[seg_];                                  \
        const __nv_bfloat16* Bg_ = Bseg[seg_];                                  \
        uint32_t sA_ = sb + (uint32_t)(buf) * STAGE;                            \
        uint32_t sB_ = sA_ + ABYTES;                                            \
        _Pragma("unroll")                                                       \
        for (int i_ = 0; i_ < 4; i_++) {                                        \
            int idx_ = tid + i_ * 256;                                          \
            int r_ = idx_ >> 3, c_ = idx_ & 7;                                  \
            int gm_ = m0 + r_;                                                  \
            bool v_ = gm_ < jb.M;                                               \
            int gmc_ = v_ ? gm_ : (jb.M - 1);                                   \
            cp16(sA_ + r_ * 144 + c_ * 16,                                      \
                 Ag_ + (size_t)gmc_ * 256 + k0_ + c_ * 8, v_);                  \
        }                                                                       \
        _Pragma("unroll")                                                       \
        for (int i_ = 0; i_ < 4; i_++) {                                        \
            int idx_ = tid + i_ * 256;                                          \
            int r_ = idx_ >> 3, c_ = idx_ & 7;                                  \
            cp16(sB_ + r_ * 144 + c_ * 16,                                      \
                 Bg_ + (size_t)(n0 + r_) * 256 + k0_ + c_ * 8, true);           \
        }                                                                       \
        cp_commit();                                                            \
    } while (0)

    ISSUE_LOAD(0, 0);
    ISSUE_LOAD(1, 1);
#pragma unroll 1
    for (int c = 0; c < 12; c++) {
        if (c < 11) asm volatile("cp.async.wait_group 1;");
        else        asm volatile("cp.async.wait_group 0;");
        __syncthreads();
        if (c + 2 < 12) ISSUE_LOAD(c + 2, (c + 2) % 3);
        uint32_t sA = sb + (uint32_t)(c % 3) * STAGE;
        uint32_t sB = sA + ABYTES;
#pragma unroll
        for (int k16 = 0; k16 < 4; k16++) {
            uint32_t a[2][4];
#pragma unroll
            for (int i = 0; i < 2; i++) {
                uint32_t row = warp_m * 32 + i * 16 + (lane & 15);
                ldsm_x4(a[i], sA + row * 144 + k16 * 32 + ((lane >> 4) * 16));
            }
            uint32_t b[8][2];
#pragma unroll
            for (int j = 0; j < 4; j++) {
                uint32_t row = warp_n * 64 + j * 16 + (lane & 7) + (((lane >> 4) & 1) << 3);
                uint32_t t[4];
                ldsm_x4(t, sB + row * 144 + k16 * 32 + (((lane >> 3) & 1) << 4));
                b[2 * j][0] = t[0]; b[2 * j][1] = t[1];
                b[2 * j + 1][0] = t[2]; b[2 * j + 1][1] = t[3];
            }
#pragma unroll
            for (int i = 0; i < 2; i++)
#pragma unroll
                for (int n = 0; n < 8; n++) mma_bf16(acc[i][n], a[i], b[n]);
        }
    }
    __syncthreads();

    // ---- epilogue: fp16 C stores + fused fp32 dot partials ----
    bool need_dots = (jb.a1 != nullptr) || (jb.a2 != nullptr);
    float* sdot = (float*)smem;
    if (need_dots) {
        if (tid < 256) sdot[tid] = 0.f;
        __syncthreads();
    }

#pragma unroll
    for (int i = 0; i < 2; i++) {
        int rloc = warp_m * 32 + i * 16 + (lane >> 2);
        int rowA = m0 + rloc;
        int rowB = rowA + 8;
        float d1a = 0.f, d1b = 0.f, d2a = 0.f, d2b = 0.f;
#pragma unroll
        for (int n = 0; n < 8; n++) {
            int col = n0 + warp_n * 64 + n * 8 + 2 * (lane & 3);
            float b0 = 0.f, b1 = 0.f;
            if (jb.bias) { b0 = __ldg(jb.bias + col); b1 = __ldg(jb.bias + col + 1); }
            float c0 = acc[i][n][0] + b0, c1 = acc[i][n][1] + b1;
            float c2 = acc[i][n][2] + b0, c3 = acc[i][n][3] + b1;
            __half2* base = (__half2*)jb.C;
            if (rowA < jb.M) base[((size_t)rowA * 256 + col) >> 1] = __floats2half2_rn(c0, c1);
            if (rowB < jb.M) base[((size_t)rowB * 256 + col) >> 1] = __floats2half2_rn(c2, c3);
            if (jb.a1) {
                float q0 = __ldg(jb.a1 + col), q1 = __ldg(jb.a1 + col + 1);
                d1a += c0 * q0 + c1 * q1;
                d1b += c2 * q0 + c3 * q1;
            }
            if (jb.a2) {
                float q0 = __ldg(jb.a2 + col), q1 = __ldg(jb.a2 + col + 1);
                d2a += c0 * q0 + c1 * q1;
                d2b += c2 * q0 + c3 * q1;
            }
        }
        if (jb.a1) {
            d1a += __shfl_xor_sync(0xffffffffu, d1a, 1);
            d1a += __shfl_xor_sync(0xffffffffu, d1a, 2);
            d1b += __shfl_xor_sync(0xffffffffu, d1b, 1);
            d1b += __shfl_xor_sync(0xffffffffu, d1b, 2);
            if ((lane & 3) == 0) {
                atomicAdd(&sdot[rloc], d1a);
                atomicAdd(&sdot[rloc + 8], d1b);
            }
        }
        if (jb.a2) {
            d2a += __shfl_xor_sync(0xffffffffu, d2a, 1);
            d2a += __shfl_xor_sync(0xffffffffu, d2a, 2);
            d2b += __shfl_xor_sync(0xffffffffu, d2b, 1);
            d2b += __shfl_xor_sync(0xffffffffu, d2b, 2);
            if ((lane & 3) == 0) {
                atomicAdd(&sdot[128 + rloc], d2a);
                atomicAdd(&sdot[128 + rloc + 8], d2b);
            }
        }
    }
    if (need_dots) {
        __syncthreads();
        if (tid < 128 && m0 + tid < jb.M) {
            if (jb.s1) atomicAdd(&jb.s1[m0 + tid], sdot[tid]);
            if (jb.s2) atomicAdd(&jb.s2[m0 + tid], sdot[128 + tid]);
        }
    }
}

// ==================== warp-level softmax-aggregation (fp16 gather) ====================
__device__ __forceinline__ void warp_rel_agg(
    const int* __restrict__ srcs, int e0, int deg, float sd,
    const float* __restrict__ s_src, const __half* __restrict__ wx,
    int lane, float4& acc0, float4& acc1) {
    acc0 = make_float4(0.f, 0.f, 0.f, 0.f);
    acc1 = make_float4(0.f, 0.f, 0.f, 0.f);
    if (deg <= 0) return;
    float m = -1e30f;
    for (int base = 0; base < deg; base += 32) {
        int e = base + lane;
        float sc = -1e30f;
        if (e < deg) {
            float x = s_src[srcs[e0 + e]] + sd;
            sc = x > 0.f ? x : 0.2f * x;
        }
#pragma unroll
        for (int o = 16; o; o >>= 1) sc = fmaxf(sc, __shfl_xor_sync(0xffffffffu, sc, o));
        m = fmaxf(m, sc);
    }
    float ssum = 0.f;
    for (int base = 0; base < deg; base += 32) {
        int e = base + lane;
        int s = 0; float wgt = 0.f;
        if (e < deg) {
            s = srcs[e0 + e];
            float x = s_src[s] + sd;
            x = x > 0.f ? x : 0.2f * x;
            wgt = expf(x - m);
        }
        float part = wgt;
#pragma unroll
        for (int o = 16; o; o >>= 1) part += __shfl_xor_sync(0xffffffffu, part, o);
        ssum += part;
        int cnt = min(32, deg - base);
        int j = 0;
        for (; j + 2 <= cnt; j += 2) {
            float wj0 = __shfl_sync(0xffffffffu, wgt, j);
            float wj1 = __shfl_sync(0xffffffffu, wgt, j + 1);
            int sj0 = __shfl_sync(0xffffffffu, s, j);
            int sj1 = __shfl_sync(0xffffffffu, s, j + 1);
            uint4 p0 = *((const uint4*)(wx + (size_t)sj0 * D) + lane);
            uint4 p1 = *((const uint4*)(wx + (size_t)sj1 * D) + lane);
            float2 f;
            f = __half22float2(*(__half2*)&p0.x); acc0.x += wj0 * f.x; acc0.y += wj0 * f.y;
            f = __half22float2(*(__half2*)&p0.y); acc0.z += wj0 * f.x; acc0.w += wj0 * f.y;
            f = __half22float2(*(__half2*)&p0.z); acc1.x += wj0 * f.x; acc1.y += wj0 * f.y;
            f = __half22float2(*(__half2*)&p0.w); acc1.z += wj0 * f.x; acc1.w += wj0 * f.y;
            f = __half22float2(*(__half2*)&p1.x); acc0.x += wj1 * f.x; acc0.y += wj1 * f.y;
            f = __half22float2(*(__half2*)&p1.y); acc0.z += wj1 * f.x; acc0.w += wj1 * f.y;
            f = __half22float2(*(__half2*)&p1.z); acc1.x += wj1 * f.x; acc1.y += wj1 * f.y;
            f = __half22float2(*(__half2*)&p1.w); acc1.z += wj1 * f.x; acc1.w += wj1 * f.y;
        }
        if (j < cnt) {
            float wj = __shfl_sync(0xffffffffu, wgt, j);
            int sj = __shfl_sync(0xffffffffu, s, j);
            uint4 p = *((const uint4*)(wx + (size_t)sj * D) + lane);
            float2 f;
            f = __half22float2(*(__half2*)&p.x); acc0.x += wj * f.x; acc0.y += wj * f.y;
            f = __half22float2(*(__half2*)&p.y); acc0.z += wj * f.x; acc0.w += wj * f.y;
            f = __half22float2(*(__half2*)&p.z); acc1.x += wj * f.x; acc1.y += wj * f.y;
            f = __half22float2(*(__half2*)&p.w); acc1.z += wj * f.x; acc1.w += wj * f.y;
        }
    }
    float inv = 1.f / ssum;
    acc0.x *= inv; acc0.y *= inv; acc0.z *= inv; acc0.w *= inv;
    acc1.x *= inv; acc1.y *= inv; acc1.z *= inv; acc1.w *= inv;
}

__device__ __forceinline__ void load_half8(const __half* p, int b, int lane,
                                           float4& f0, float4& f1) {
    uint4 u = *((const uint4*)(p + (size_t)b * D) + lane);
    float2 t;
    t = __half22float2(*(__half2*)&u.x); f0.x = t.x; f0.y = t.y;
    t = __half22float2(*(__half2*)&u.y); f0.z = t.x; f0.w = t.y;
    t = __half22float2(*(__half2*)&u.z); f1.x = t.x; f1.y = t.y;
    t = __half22float2(*(__half2*)&u.w); f1.z = t.x; f1.w = t.y;
}

// ==================== combined aggregation -> output ====================
struct AggArgs {
    const int *srcs0, *off0; const float *ssrc0, *sdst0; const __half* wx0;
    const int *srcs1, *off1; const float *ssrc1, *sdst1; const __half* wx1;
    const int *srcs2, *off2; const float *ssrc2, *sdst2; const __half* wx2;
    const __half *selfa, *selfp; const float* q;
    float* out; int Na, Np, nblocksA;
};

__global__ void agg_all(AggArgs a) {
    int w = threadIdx.x >> 5, lane = threadIdx.x & 31;
    if (blockIdx.x < (unsigned)a.nblocksA) {
        int b = blockIdx.x * 8 + w;
        if (b >= a.Na) return;
        int e0 = a.off1[b];
        int deg = a.off1[b + 1] - e0;
        float4 x0, x1;
        warp_rel_agg(a.srcs1, e0, deg, deg > 0 ? a.sdst1[b] : 0.f, a.ssrc1, a.wx1, lane, x0, x1);
        float4 s0, s1;
        load_half8(a.selfa, b, lane, s0, s1);
        float v;
        v = s0.x + x0.x; x0.x = v > 0.f ? v : expm1f(v);
        v = s0.y + x0.y; x0.y = v > 0.f ? v : expm1f(v);
        v = s0.z + x0.z; x0.z = v > 0.f ? v : expm1f(v);
        v = s0.w + x0.w; x0.w = v > 0.f ? v : expm1f(v);
        v = s1.x + x1.x; x1.x = v > 0.f ? v : expm1f(v);
        v = s1.y + x1.y; x1.y = v > 0.f ? v : expm1f(v);
        v = s1.z + x1.z; x1.z = v > 0.f ? v : expm1f(v);
        v = s1.w + x1.w; x1.w = v > 0.f ? v : expm1f(v);
        float4* o = (float4*)(a.out + (size_t)b * D) + lane * 2;
        o[0] = x0; o[1] = x1;
    } else {
        int b = (blockIdx.x - a.nblocksA) * 8 + w;
        if (b >= a.Np) return;
        int e0a = a.off0[b];
        int dega = a.off0[b + 1] - e0a;
        float4 x0, x1;
        warp_rel_agg(a.srcs0, e0a, dega, dega > 0 ? a.sdst0[b] : 0.f, a.ssrc0, a.wx0, lane, x0, x1);
        int e0c = a.off2[b];
        int degc = a.off2[b + 1] - e0c;
        float4 c0, c1;
        warp_rel_agg(a.srcs2, e0c, degc, degc > 0 ? a.sdst2[b] : 0.f, a.ssrc2, a.wx2, lane, c0, c1);

        const float4* q4 = (const float4*)a.q + lane * 2;
        float4 q0 = __ldg(q4), q1 = __ldg(q4 + 1);
        float t1 = tanhf(x0.x) * q0.x + tanhf(x0.y) * q0.y + tanhf(x0.z) * q0.z + tanhf(x0.w) * q0.w
                 + tanhf(x1.x) * q1.x + tanhf(x1.y) * q1.y + tanhf(x1.z) * q1.z + tanhf(x1.w) * q1.w;
        float t2 = tanhf(c0.x) * q0.x + tanhf(c0.y) * q0.y + tanhf(c0.z) * q0.z + tanhf(c0.w) * q0.w
                 + tanhf(c1.x) * q1.x + tanhf(c1.y) * q1.y + tanhf(c1.z) * q1.z + tanhf(c1.w) * q1.w;
#pragma unroll
        for (int o = 16; o; o >>= 1) {
            t1 += __shfl_xor_sync(0xffffffffu, t1, o);
            t2 += __shfl_xor_sync(0xffffffffu, t2, o);
        }
        float mm = fmaxf(t1, t2);
        float w1 = expf(t1 - mm), w2 = expf(t2 - mm);
        float z = 1.f / (w1 + w2);
        w1 *= z; w2 *= z;
        float4 s0, s1;
        load_half8(a.selfp, b, lane, s0, s1);
        float v;
        v = s0.x + w1 * x0.x + w2 * c0.x; s0.x = v > 0.f ? v : expm1f(v);
        v = s0.y + w1 * x0.y + w2 * c0.y; s0.y = v > 0.f ? v : expm1f(v);
        v = s0.z + w1 * x0.z + w2 * c0.z; s0.z = v > 0.f ? v : expm1f(v);
        v = s0.w + w1 * x0.w + w2 * c0.w; s0.w = v > 0.f ? v : expm1f(v);
        v = s1.x + w1 * x1.x + w2 * c1.x; s1.x = v > 0.f ? v : expm1f(v);
        v = s1.y + w1 * x1.y + w2 * c1.y; s1.y = v > 0.f ? v : expm1f(v);
        v = s1.z + w1 * x1.z + w2 * c1.z; s1.z = v > 0.f ? v : expm1f(v);
        v = s1.w + w1 * x1.w + w2 * c1.w; s1.w = v > 0.f ? v : expm1f(v);
        float4* o = (float4*)(a.out + (size_t)(a.Na + b) * D) + lane * 2;
        o[0] = s0; o[1] = s1;
    }
}

// ==================== host launch ====================
extern "C" void kernel_launch(void* const* d_in, const int* in_sizes, int n_in,
                              void* d_out, int out_size) {
    const float* h_author = (const float*)d_in[0];
    const float* h_paper  = (const float*)d_in[1];
    const int* ei_ap = (const int*)d_in[2];
    const int* ei_pa = (const int*)d_in[3];
    const int* ei_pp = (const int*)d_in[4];
    const float* W_ap = (const float*)d_in[5];
    const float* a_src_ap = (const float*)d_in[6];
    const float* a_dst_ap = (const float*)d_in[7];
    const float* W_pa = (const float*)d_in[8];
    const float* a_src_pa = (const float*)d_in[9];
    const float* a_dst_pa = (const float*)d_in[10];
    const float* W_pp = (const float*)d_in[11];
    const float* a_src_pp = (const float*)d_in[12];
    const float* a_dst_pp = (const float*)d_in[13];
    const float* Wself_a = (const float*)d_in[14];
    const float* bself_a = (const float*)d_in[15];
    const float* Wself_p = (const float*)d_in[16];
    const float* bself_p = (const float*)d_in[17];
    const float* q_paper  = (const float*)d_in[19];

    int Na = in_sizes[0] / D;
    int Np = in_sizes[1] / D;
    int Eap = in_sizes[2] / 2;
    int Epa = in_sizes[3] / 2;
    int Epp = in_sizes[4] / 2;

    float *wx, *svec, *vv;
    int *cnt, *off, *cur, *srcs, *bsums;
    __nv_bfloat16 *ha, *hp, *wsp;
    cudaGetSymbolAddress((void**)&wx, g_wx);
    cudaGetSymbolAddress((void**)&svec, g_s);
    cudaGetSymbolAddress((void**)&vv, g_v);
    cudaGetSymbolAddress((void**)&cnt, g_cnt);
    cudaGetSymbolAddress((void**)&off, g_off);
    cudaGetSymbolAddress((void**)&cur, g_cur);
    cudaGetSymbolAddress((void**)&srcs, g_srcs);
    cudaGetSymbolAddress((void**)&bsums, g_bsums);
    cudaGetSymbolAddress((void**)&ha, g_ha);
    cudaGetSymbolAddress((void**)&hp, g_hp);
    cudaGetSymbolAddress((void**)&wsp, g_wsplit);

    const size_t WXS = (size_t)NMAX * D;
    float* wxp[7];
    for (int i = 0; i < 7; i++) wxp[i] = wx + i * WXS;
    __half* hx0 = (__half*)wxp[0];
    __half* hx1 = (__half*)wxp[2];
    __half* hx2 = (__half*)wxp[4];
    __half* hselfA = (__half*)wxp[5];
    __half* hselfP = (__half*)wxp[6];
    float* sp[6];
    for (int i = 0; i < 6; i++) sp[i] = svec + (size_t)i * NMAX;
    __nv_bfloat16* haHi = ha;            __nv_bfloat16* haLo = ha + WXS;
    __nv_bfloat16* hpHi = hp;            __nv_bfloat16* hpLo = hp + WXS;
    __nv_bfloat16* wHi[5]; __nv_bfloat16* wLo[5];
    for (int i = 0; i < 5; i++) { wHi[i] = wsp + (size_t)(2 * i) * D * D; wLo[i] = wHi[i] + D * D; }

    // (1) split + zero
    SplitZeroArgs sz;
    sz.j[0] = {h_author, haHi, haLo, Na * D};
    sz.j[1] = {h_paper,  hpHi, hpLo, Np * D};
    sz.j[2] = {W_ap,    wHi[0], wLo[0], D * D};
    sz.j[3] = {W_pa,    wHi[1], wLo[1], D * D};
    sz.j[4] = {W_pp,    wHi[2], wLo[2], D * D};
    sz.j[5] = {Wself_a, wHi[3], wLo[3], D * D};
    sz.j[6] = {Wself_p, wHi[4], wLo[4], D * D};
    sz.cnt = cnt; sz.svec = svec;
    split_zero<<<dim3(148, 8), 256>>>(sz);

    // (2) histogram   (3) scanA
    int Emax3 = max(Eap, max(Epa, Epp));
    hist3_kernel<<<dim3((Emax3 + 255) / 256, 3), 256>>>(ei_ap, ei_pa, ei_pp, Eap, Epa, Epp, cnt);
    scanA_kernel<<<dim3(49, 3), 1024>>>(cnt, off, bsums, Np, Na, Np);

    // (4) batched HMMA GEMMs  [4th launch -> ncu window]
    GemmJobs gj;
    gj.j[0] = {haHi, haLo, wHi[0], wLo[0], hx0, nullptr, a_src_ap, sp[0], nullptr, nullptr, Na, 0};
    gj.j[1] = {hpHi, hpLo, wHi[1], wLo[1], hx1, nullptr, a_src_pa, sp[2], nullptr, nullptr, Np, 0};
    gj.j[2] = {hpHi, hpLo, wHi[2], wLo[2], hx2, nullptr, a_src_pp, sp[4], a_dst_pp, sp[5], Np, 0};
    gj.j[3] = {haHi, haLo, wHi[3], wLo[3], hselfA, bself_a, nullptr, nullptr, nullptr, nullptr, Na, 0};
    gj.j[4] = {hpHi, hpLo, wHi[4], wLo[4], hselfP, bself_p, nullptr, nullptr, nullptr, nullptr, Np, 0};
    int maxM = max(Na, Np);
    cudaFuncSetAttribute(gemm_batch, cudaFuncAttributeMaxDynamicSharedMemorySize, GSM_BYTES);
    gemm_batch<<<dim3((maxM + 127) / 128, 2, 5), 256, GSM_BYTES>>>(gj);

    // (5) scanB + matvec (merged)   (6) scanC
    scanB_matvec<<<5, 256>>>(bsums, off, Np, Na, Np, W_ap, a_dst_ap, W_pa, a_dst_pa, vv);
    scanC_kernel<<<dim3(49, 3), 1024>>>(bsums, off, cur, Np, Na, Np);

    // (7) scatter + dotv (merged)
    int sx = max((Emax3 + 255) / 256, (maxM + 7) / 8);
    scatter_dotv<<<dim3(sx, 5), 256>>>(ei_ap, ei_pa, ei_pp, Eap, Epa, Epp, cur, srcs,
                                       h_paper, h_author, vv, sp[1], sp[3], Np, Na);

    // (8) combined aggregation -> output
    float* out = (float*)d_out;
    AggArgs aa;
    aa.srcs0 = srcs + 0 * EMAX; aa.off0 = off + 0 * (NMAX + 1);
    aa.ssrc0 = sp[0]; aa.sdst0 = sp[1]; aa.wx0 = hx0;
    aa.srcs1 = srcs + 1 * EMAX; aa.off1 = off + 1 * (NMAX + 1);
    aa.ssrc1 = sp[2]; aa.sdst1 = sp[3]; aa.wx1 = hx1;
    aa.srcs2 = srcs + 2 * EMAX; aa.off2 = off + 2 * (NMAX + 1);
    aa.ssrc2 = sp[4]; aa.sdst2 = sp[5]; aa.wx2 = hx2;
    aa.selfa = hselfA; aa.selfp = hselfP; aa.q = q_paper;
    aa.out = out; aa.Na = Na; aa.Np = Np;
    aa.nblocksA = (Na + 7) / 8;
    int nblocksP = (Np + 7) / 8;
    agg_all<<<aa.nblocksA + nblocksP, 256>>>(aa);
}

// round 17
// speedup vs baseline: 1.0300x; 1.0085x over previous
#include <cuda_runtime.h>
#include <cuda_bf16.h>
#include <cuda_fp16.h>
#include <cstdint>

#define D 256
#define NMAX 50000
#define EMAX 300000

// ==================== static device scratch ====================
// slots 0,2,4 = fp16 gather sources (ap,pa,pp); slots 5,6 = fp16 self transforms
__device__ float g_wx[(size_t)7 * NMAX * D];
__device__ float g_s[6 * NMAX];
__device__ float g_v[2 * D];
__device__ int   g_cnt[3 * NMAX];
__device__ int   g_off[3 * (NMAX + 1)];
__device__ int   g_cur[3 * NMAX];
__device__ int   g_srcs[3 * EMAX];
__device__ int   g_bsums[3 * 64];
__device__ __nv_bfloat16 g_ha[2 * (size_t)NMAX * D];
__device__ __nv_bfloat16 g_hp[2 * (size_t)NMAX * D];
__device__ __nv_bfloat16 g_wsplit[5 * 2 * D * D];

// ==================== low-level helpers ====================
__device__ __forceinline__ uint32_t smem_to_u32(const void* p) {
    uint32_t a;
    asm("{ .reg .u64 t; cvta.to.shared.u64 t, %1; cvt.u32.u64 %0, t; }" : "=r"(a) : "l"(p));
    return a;
}
__device__ __forceinline__ void cp16(uint32_t saddr, const void* g, bool valid) {
    asm volatile("cp.async.cg.shared.global [%0], [%1], 16, %2;"
                 :: "r"(saddr), "l"(g), "r"(valid ? 16 : 0));
}
__device__ __forceinline__ void cp_commit() { asm volatile("cp.async.commit_group;"); }
__device__ __forceinline__ void ldsm_x4(uint32_t* r, uint32_t addr) {
    asm volatile("ldmatrix.sync.aligned.m8n8.x4.shared.b16 {%0,%1,%2,%3}, [%4];"
                 : "=r"(r[0]), "=r"(r[1]), "=r"(r[2]), "=r"(r[3]) : "r"(addr));
}
__device__ __forceinline__ void mma_bf16(float* c, const uint32_t* a, const uint32_t* b) {
    asm volatile(
        "mma.sync.aligned.m16n8k16.row.col.f32.bf16.bf16.f32 "
        "{%0,%1,%2,%3}, {%4,%5,%6,%7}, {%8,%9}, {%0,%1,%2,%3};"
        : "+f"(c[0]), "+f"(c[1]), "+f"(c[2]), "+f"(c[3])
        : "r"(a[0]), "r"(a[1]), "r"(a[2]), "r"(a[3]), "r"(b[0]), "r"(b[1]));
}

// ==================== split + zero (merged) ====================
struct SplitJob { const float* x; __nv_bfloat16* hi; __nv_bfloat16* lo; int n; };
struct SplitZeroArgs { SplitJob j[7]; int* cnt; float* svec; };

__global__ void split_zero(SplitZeroArgs a) {
    if (blockIdx.y == 7) {
        int total = 6 * NMAX;
        for (int i = blockIdx.x * blockDim.x + threadIdx.x; i < total;
             i += gridDim.x * blockDim.x) {
            if (i < 3 * NMAX) a.cnt[i] = 0;
            a.svec[i] = 0.f;
        }
        return;
    }
    SplitJob jb = a.j[blockIdx.y];
    int n4 = jb.n >> 2;
    for (int i = blockIdx.x * blockDim.x + threadIdx.x; i < n4; i += gridDim.x * blockDim.x) {
        float4 v = ((const float4*)jb.x)[i];
        float vs[4] = {v.x, v.y, v.z, v.w};
        unsigned short hs[4], ls[4];
#pragma unroll
        for (int k = 0; k < 4; k++) {
            __nv_bfloat16 h = __float2bfloat16(vs[k]);
            float r = vs[k] - __bfloat162float(h);
            __nv_bfloat16 l = __float2bfloat16(r);
            hs[k] = *(unsigned short*)&h;
            ls[k] = *(unsigned short*)&l;
        }
        ((uint2*)jb.hi)[i] = make_uint2((uint32_t)hs[0] | ((uint32_t)hs[1] << 16),
                                        (uint32_t)hs[2] | ((uint32_t)hs[3] << 16));
        ((uint2*)jb.lo)[i] = make_uint2((uint32_t)ls[0] | ((uint32_t)ls[1] << 16),
                                        (uint32_t)ls[2] | ((uint32_t)ls[3] << 16));
    }
}

// ==================== CSR build ====================
__global__ void hist3_kernel(const int* e0, const int* e1, const int* e2,
                             int E0, int E1, int E2, int* cnt) {
    int r = blockIdx.y;
    const int* e = r == 0 ? e0 : (r == 1 ? e1 : e2);
    int E = r == 0 ? E0 : (r == 1 ? E1 : E2);
    int i = blockIdx.x * blockDim.x + threadIdx.x;
    if (i < E) atomicAdd(&cnt[r * NMAX + e[E + i]], 1);
}
__global__ void scanA_kernel(const int* cnt, int* off, int* bsums, int n0, int n1, int n2) {
    int r = blockIdx.y;
    int n = r == 0 ? n0 : (r == 1 ? n1 : n2);
    int idx = blockIdx.x * 1024 + threadIdx.x;
    int tid = threadIdx.x, lane = tid & 31, w = tid >> 5;
    __shared__ int wsum[32];
    int v = idx < n ? cnt[r * NMAX + idx] : 0;
    int x = v;
#pragma unroll
    for (int o = 1; o < 32; o <<= 1) {
        int y = __shfl_up_sync(0xffffffffu, x, o);
        if (lane >= o) x += y;
    }
    if (lane == 31) wsum[w] = x;
    __syncthreads();
    if (w == 0) {
        int s = wsum[lane];
#pragma unroll
        for (int o = 1; o < 32; o <<= 1) {
            int y = __shfl_up_sync(0xffffffffu, s, o);
            if (lane >= o) s += y;
        }
        wsum[lane] = s;
    }
    __syncthreads();
    int prefix = w ? wsum[w - 1] : 0;
    int incl = prefix + x;
    if (idx < n) off[r * (NMAX + 1) + idx] = incl - v;
    if (tid == 1023) bsums[r * 64 + blockIdx.x] = incl;
}
// scanB (x<3) + matvec (x=3,4) merged
__global__ void scanB_matvec(int* bsums, int* off, int n0, int n1, int n2,
                             const float* W0, const float* a0,
                             const float* W1, const float* a1, float* v) {
    if (blockIdx.x >= 3) {
        int r = blockIdx.x - 3;
        const float* W = r ? W1 : W0;
        const float* a = r ? a1 : a0;
        int k = threadIdx.x;
        float s0 = 0.f, s1 = 0.f, s2 = 0.f, s3 = 0.f;
#pragma unroll 4
        for (int n = 0; n < D; n += 4) {
            s0 += __ldg(&a[n + 0]) * __ldg(&W[(n + 0) * D + k]);
            s1 += __ldg(&a[n + 1]) * __ldg(&W[(n + 1) * D + k]);
            s2 += __ldg(&a[n + 2]) * __ldg(&W[(n + 2) * D + k]);
            s3 += __ldg(&a[n + 3]) * __ldg(&W[(n + 3) * D + k]);
        }
        v[r * D + k] = (s0 + s1) + (s2 + s3);
        return;
    }
    if (threadIdx.x >= 64) return;
    int r = blockIdx.x;
    int n = r == 0 ? n0 : (r == 1 ? n1 : n2);
    int nb = (n + 1023) >> 10;
    int t = threadIdx.x, lane = t & 31, w = t >> 5;
    __shared__ int sh[2];
    int v2 = t < nb ? bsums[r * 64 + t] : 0;
    int x = v2;
#pragma unroll
    for (int o = 1; o < 32; o <<= 1) {
        int y = __shfl_up_sync(0xffffffffu, x, o);
        if (lane >= o) x += y;
    }
    if (lane == 31) sh[w] = x;
    __syncthreads();
    int incl = x + (w == 1 ? sh[0] : 0);
    if (t < 64) bsums[r * 64 + t] = incl - v2;
    if (t == nb - 1) off[r * (NMAX + 1) + n] = incl;
}
__global__ void scanC_kernel(const int* bsums, int* off, int* cur, int n0, int n1, int n2) {
    int r = blockIdx.y;
    int n = r == 0 ? n0 : (r == 1 ? n1 : n2);
    int idx = blockIdx.x * 1024 + threadIdx.x;
    if (idx < n) {
        int v = off[r * (NMAX + 1) + idx] + bsums[r * 64 + blockIdx.x];
        off[r * (NMAX + 1) + idx] = v;
        cur[r * NMAX + idx] = v;
    }
}
// scatter (y<3) + dotv (y=3,4) merged
__global__ void scatter_dotv(const int* e0, const int* e1, const int* e2,
                             int E0, int E1, int E2, int* cur, int* srcs,
                             const float* hP, const float* hA, const float* v,
                             float* sOut0, float* sOut1, int Np, int Na) {
    int r = blockIdx.y;
    if (r < 3) {
        const int* e = r == 0 ? e0 : (r == 1 ? e1 : e2);
        int E = r == 0 ? E0 : (r == 1 ? E1 : E2);
        int i = blockIdx.x * blockDim.x + threadIdx.x;
        if (i < E) {
            int p = atomicAdd(&cur[r * NMAX + e[E + i]], 1);
            srcs[r * EMAX + p] = e[i];
        }
        return;
    }
    int rr = r - 3;
    const float* x = rr ? hA : hP;
    const float* vv = v + rr * D;
    float* out = rr ? sOut1 : sOut0;
    int n = rr ? Na : Np;
    int idx = blockIdx.x * 8 + (threadIdx.x >> 5);
    if (idx >= n) return;
    int lane = threadIdx.x & 31;
    const float4* row = (const float4*)(x + (size_t)idx * D) + lane * 2;
    const float4* v4 = (const float4*)vv + lane * 2;
    float4 r0 = row[0], r1 = row[1];
    float4 q0 = __ldg(v4), q1 = __ldg(v4 + 1);
    float s = r0.x * q0.x + r0.y * q0.y + r0.z * q0.z + r0.w * q0.w
            + r1.x * q1.x + r1.y * q1.y + r1.z * q1.z + r1.w * q1.w;
#pragma unroll
    for (int o = 16; o; o >>= 1) s += __shfl_xor_sync(0xffffffffu, s, o);
    if (lane == 0) out[idx] = s;
}

// ==================== batched HMMA GEMM: 128x128 tiles, 2 CTA/SM ====================
struct GemmJob {
    const __nv_bfloat16 *Ahi, *Alo, *Bhi, *Blo;
    __half* C; const float* bias;
    const float* a1; float* s1;
    const float* a2; float* s2;
    int M; int pad;
};
struct GemmJobs { GemmJob j[5]; };

#define ABYTES (128 * 144)
#define BBYTES (128 * 144)
#define STAGE  (ABYTES + BBYTES)
#define GSM_BYTES (3 * STAGE)

__global__ __launch_bounds__(256, 2) void gemm_batch(GemmJobs jobs) {
    extern __shared__ char smem[];
    GemmJob jb = jobs.j[blockIdx.z];
    int m0 = blockIdx.x * 128;
    if (m0 >= jb.M) return;
    int n0 = blockIdx.y * 128;
    uint32_t sb = smem_to_u32(smem);
    int tid = threadIdx.x;
    int wid = tid >> 5, lane = tid & 31;
    int warp_m = wid & 3, warp_n = wid >> 2;

    float acc[2][8][4];
#pragma unroll
    for (int i = 0; i < 2; i++)
#pragma unroll
        for (int n = 0; n < 8; n++)
#pragma unroll
            for (int k = 0; k < 4; k++) acc[i][n][k] = 0.f;

    const __nv_bfloat16* Aseg[3] = {jb.Ahi, jb.Alo, jb.Ahi};
    const __nv_bfloat16* Bseg[3] = {jb.Bhi, jb.Bhi, jb.Blo};

#define ISSUE_LOAD(c, buf) do {                                                 \
        int seg_ = (c) >> 2, k0_ = ((c) & 3) * 64;                              \
        const __nv_bfloat16* Ag_ = Aseg[seg_];                                  \
        const __nv_bfloat16* Bg_ = Bseg[seg_];                                  \
        uint32_t sA_ = sb + (uint32_t)(buf) * STAGE;                            \
        uint32_t sB_ = sA_ + ABYTES;                                            \
        _Pragma("unroll")                                                       \
        for (int i_ = 0; i_ < 4; i_++) {                                        \
            int idx_ = tid + i_ * 256;                                          \
            int r_ = idx_ >> 3, c_ = idx_ & 7;                                  \
            int gm_ = m0 + r_;                                                  \
            bool v_ = gm_ < jb.M;                                               \
            int gmc_ = v_ ? gm_ : (jb.M - 1);                                   \
            cp16(sA_ + r_ * 144 + c_ * 16,                                      \
                 Ag_ + (size_t)gmc_ * 256 + k0_ + c_ * 8, v_);                  \
        }                                                                       \
        _Pragma("unroll")                                                       \
        for (int i_ = 0; i_ < 4; i_++) {                                        \
            int idx_ = tid + i_ * 256;                                          \
            int r_ = idx_ >> 3, c_ = idx_ & 7;                                  \
            cp16(sB_ + r_ * 144 + c_ * 16,                                      \
                 Bg_ + (size_t)(n0 + r_) * 256 + k0_ + c_ * 8, true);           \
        }                                                                       \
        cp_commit();                                                            \
    } while (0)

    ISSUE_LOAD(0, 0);
    ISSUE_LOAD(1, 1);
#pragma unroll 1
    for (int c = 0; c < 12; c++) {
        if (c < 11) asm volatile("cp.async.wait_group 1;");
        else        asm volatile("cp.async.wait_group 0;");
        __syncthreads();
        if (c + 2 < 12) ISSUE_LOAD(c + 2, (c + 2) % 3);
        uint32_t sA = sb + (uint32_t)(c % 3) * STAGE;
        uint32_t sB = sA + ABYTES;
#pragma unroll
        for (int k16 = 0; k16 < 4; k16++) {
            uint32_t a[2][4];
#pragma unroll
            for (int i = 0; i < 2; i++) {
                uint32_t row = warp_m * 32 + i * 16 + (lane & 15);
                ldsm_x4(a[i], sA + row * 144 + k16 * 32 + ((lane >> 4) * 16));
            }
            uint32_t b[8][2];
#pragma unroll
            for (int j = 0; j < 4; j++) {
                uint32_t row = warp_n * 64 + j * 16 + (lane & 7) + (((lane >> 4) & 1) << 3);
                uint32_t t[4];
                ldsm_x4(t, sB + row * 144 + k16 * 32 + (((lane >> 3) & 1) << 4));
                b[2 * j][0] = t[0]; b[2 * j][1] = t[1];
                b[2 * j + 1][0] = t[2]; b[2 * j + 1][1] = t[3];
            }
#pragma unroll
            for (int i = 0; i < 2; i++)
#pragma unroll
                for (int n = 0; n < 8; n++) mma_bf16(acc[i][n], a[i], b[n]);
        }
    }
    __syncthreads();

    // ---- epilogue: fp16 C stores + fused fp32 dot partials ----
    bool need_dots = (jb.a1 != nullptr) || (jb.a2 != nullptr);
    float* sdot = (float*)smem;
    if (need_dots) {
        if (tid < 256) sdot[tid] = 0.f;
        __syncthreads();
    }

#pragma unroll
    for (int i = 0; i < 2; i++) {
        int rloc = warp_m * 32 + i * 16 + (lane >> 2);
        int rowA = m0 + rloc;
        int rowB = rowA + 8;
        float d1a = 0.f, d1b = 0.f, d2a = 0.f, d2b = 0.f;
#pragma unroll
        for (int n = 0; n < 8; n++) {
            int col = n0 + warp_n * 64 + n * 8 + 2 * (lane & 3);
            float b0 = 0.f, b1 = 0.f;
            if (jb.bias) { b0 = __ldg(jb.bias + col); b1 = __ldg(jb.bias + col + 1); }
            float c0 = acc[i][n][0] + b0, c1 = acc[i][n][1] + b1;
            float c2 = acc[i][n][2] + b0, c3 = acc[i][n][3] + b1;
            __half2* base = (__half2*)jb.C;
            if (rowA < jb.M) base[((size_t)rowA * 256 + col) >> 1] = __floats2half2_rn(c0, c1);
            if (rowB < jb.M) base[((size_t)rowB * 256 + col) >> 1] = __floats2half2_rn(c2, c3);
            if (jb.a1) {
                float q0 = __ldg(jb.a1 + col), q1 = __ldg(jb.a1 + col + 1);
                d1a += c0 * q0 + c1 * q1;
                d1b += c2 * q0 + c3 * q1;
            }
            if (jb.a2) {
                float q0 = __ldg(jb.a2 + col), q1 = __ldg(jb.a2 + col + 1);
                d2a += c0 * q0 + c1 * q1;
                d2b += c2 * q0 + c3 * q1;
            }
        }
        if (jb.a1) {
            d1a += __shfl_xor_sync(0xffffffffu, d1a, 1);
            d1a += __shfl_xor_sync(0xffffffffu, d1a, 2);
            d1b += __shfl_xor_sync(0xffffffffu, d1b, 1);
            d1b += __shfl_xor_sync(0xffffffffu, d1b, 2);
            if ((lane & 3) == 0) {
                atomicAdd(&sdot[rloc], d1a);
                atomicAdd(&sdot[rloc + 8], d1b);
            }
        }
        if (jb.a2) {
            d2a += __shfl_xor_sync(0xffffffffu, d2a, 1);
            d2a += __shfl_xor_sync(0xffffffffu, d2a, 2);
            d2b += __shfl_xor_sync(0xffffffffu, d2b, 1);
            d2b += __shfl_xor_sync(0xffffffffu, d2b, 2);
            if ((lane & 3) == 0) {
                atomicAdd(&sdot[128 + rloc], d2a);
                atomicAdd(&sdot[128 + rloc + 8], d2b);
            }
        }
    }
    if (need_dots) {
        __syncthreads();
        if (tid < 128 && m0 + tid < jb.M) {
            if (jb.s1) atomicAdd(&jb.s1[m0 + tid], sdot[tid]);
            if (jb.s2) atomicAdd(&jb.s2[m0 + tid], sdot[128 + tid]);
        }
    }
}

// ==================== warp-level softmax-aggregation (fp16 gather, 4x MLP) ===========
__device__ __forceinline__ void fma_row(float4& a0, float4& a1, float wj, const uint4& p) {
    float2 f;
    f = __half22float2(*(__half2*)&p.x); a0.x += wj * f.x; a0.y += wj * f.y;
    f = __half22float2(*(__half2*)&p.y); a0.z += wj * f.x; a0.w += wj * f.y;
    f = __half22float2(*(__half2*)&p.z); a1.x += wj * f.x; a1.y += wj * f.y;
    f = __half22float2(*(__half2*)&p.w); a1.z += wj * f.x; a1.w += wj * f.y;
}

__device__ __forceinline__ void warp_rel_agg(
    const int* __restrict__ srcs, int e0, int deg, float sd,
    const float* __restrict__ s_src, const __half* __restrict__ wx,
    int lane, float4& acc0, float4& acc1) {
    acc0 = make_float4(0.f, 0.f, 0.f, 0.f);
    acc1 = make_float4(0.f, 0.f, 0.f, 0.f);
    if (deg <= 0) return;
    float m = -1e30f;
    for (int base = 0; base < deg; base += 32) {
        int e = base + lane;
        float sc = -1e30f;
        if (e < deg) {
            float x = s_src[srcs[e0 + e]] + sd;
            sc = x > 0.f ? x : 0.2f * x;
        }
#pragma unroll
        for (int o = 16; o; o >>= 1) sc = fmaxf(sc, __shfl_xor_sync(0xffffffffu, sc, o));
        m = fmaxf(m, sc);
    }
    float ssum = 0.f;
    for (int base = 0; base < deg; base += 32) {
        int e = base + lane;
        int s = 0; float wgt = 0.f;
        if (e < deg) {
            s = srcs[e0 + e];
            float x = s_src[s] + sd;
            x = x > 0.f ? x : 0.2f * x;
            wgt = expf(x - m);
        }
        float part = wgt;
#pragma unroll
        for (int o = 16; o; o >>= 1) part += __shfl_xor_sync(0xffffffffu, part, o);
        ssum += part;
        int cnt = min(32, deg - base);
        int j = 0;
        for (; j + 4 <= cnt; j += 4) {
            float wj0 = __shfl_sync(0xffffffffu, wgt, j);
            float wj1 = __shfl_sync(0xffffffffu, wgt, j + 1);
            float wj2 = __shfl_sync(0xffffffffu, wgt, j + 2);
            float wj3 = __shfl_sync(0xffffffffu, wgt, j + 3);
            int sj0 = __shfl_sync(0xffffffffu, s, j);
            int sj1 = __shfl_sync(0xffffffffu, s, j + 1);
            int sj2 = __shfl_sync(0xffffffffu, s, j + 2);
            int sj3 = __shfl_sync(0xffffffffu, s, j + 3);
            uint4 p0 = *((const uint4*)(wx + (size_t)sj0 * D) + lane);
            uint4 p1 = *((const uint4*)(wx + (size_t)sj1 * D) + lane);
            uint4 p2 = *((const uint4*)(wx + (size_t)sj2 * D) + lane);
            uint4 p3 = *((const uint4*)(wx + (size_t)sj3 * D) + lane);
            fma_row(acc0, acc1, wj0, p0);
            fma_row(acc0, acc1, wj1, p1);
            fma_row(acc0, acc1, wj2, p2);
            fma_row(acc0, acc1, wj3, p3);
        }
        if (j + 2 <= cnt) {
            float wj0 = __shfl_sync(0xffffffffu, wgt, j);
            float wj1 = __shfl_sync(0xffffffffu, wgt, j + 1);
            int sj0 = __shfl_sync(0xffffffffu, s, j);
            int sj1 = __shfl_sync(0xffffffffu, s, j + 1);
            uint4 p0 = *((const uint4*)(wx + (size_t)sj0 * D) + lane);
            uint4 p1 = *((const uint4*)(wx + (size_t)sj1 * D) + lane);
            fma_row(acc0, acc1, wj0, p0);
            fma_row(acc0, acc1, wj1, p1);
            j += 2;
        }
        if (j < cnt) {
            float wj = __shfl_sync(0xffffffffu, wgt, j);
            int sj = __shfl_sync(0xffffffffu, s, j);
            uint4 p = *((const uint4*)(wx + (size_t)sj * D) + lane);
            fma_row(acc0, acc1, wj, p);
        }
    }
    float inv = 1.f / ssum;
    acc0.x *= inv; acc0.y *= inv; acc0.z *= inv; acc0.w *= inv;
    acc1.x *= inv; acc1.y *= inv; acc1.z *= inv; acc1.w *= inv;
}

__device__ __forceinline__ void load_half8(const __half* p, int b, int lane,
                                           float4& f0, float4& f1) {
    uint4 u = *((const uint4*)(p + (size_t)b * D) + lane);
    float2 t;
    t = __half22float2(*(__half2*)&u.x); f0.x = t.x; f0.y = t.y;
    t = __half22float2(*(__half2*)&u.y); f0.z = t.x; f0.w = t.y;
    t = __half22float2(*(__half2*)&u.z); f1.x = t.x; f1.y = t.y;
    t = __half22float2(*(__half2*)&u.w); f1.z = t.x; f1.w = t.y;
}

// ==================== combined aggregation -> output ====================
struct AggArgs {
    const int *srcs0, *off0; const float *ssrc0, *sdst0; const __half* wx0;
    const int *srcs1, *off1; const float *ssrc1, *sdst1; const __half* wx1;
    const int *srcs2, *off2; const float *ssrc2, *sdst2; const __half* wx2;
    const __half *selfa, *selfp; const float* q;
    float* out; int Na, Np, nblocksA;
};

__global__ void agg_all(AggArgs a) {
    int w = threadIdx.x >> 5, lane = threadIdx.x & 31;
    if (blockIdx.x < (unsigned)a.nblocksA) {
        int b = blockIdx.x * 8 + w;
        if (b >= a.Na) return;
        int e0 = a.off1[b];
        int deg = a.off1[b + 1] - e0;
        float4 x0, x1;
        warp_rel_agg(a.srcs1, e0, deg, deg > 0 ? a.sdst1[b] : 0.f, a.ssrc1, a.wx1, lane, x0, x1);
        float4 s0, s1;
        load_half8(a.selfa, b, lane, s0, s1);
        float v;
        v = s0.x + x0.x; x0.x = v > 0.f ? v : expm1f(v);
        v = s0.y + x0.y; x0.y = v > 0.f ? v : expm1f(v);
        v = s0.z + x0.z; x0.z = v > 0.f ? v : expm1f(v);
        v = s0.w + x0.w; x0.w = v > 0.f ? v : expm1f(v);
        v = s1.x + x1.x; x1.x = v > 0.f ? v : expm1f(v);
        v = s1.y + x1.y; x1.y = v > 0.f ? v : expm1f(v);
        v = s1.z + x1.z; x1.z = v > 0.f ? v : expm1f(v);
        v = s1.w + x1.w; x1.w = v > 0.f ? v : expm1f(v);
        float4* o = (float4*)(a.out + (size_t)b * D) + lane * 2;
        o[0] = x0; o[1] = x1;
    } else {
        int b = (blockIdx.x - a.nblocksA) * 8 + w;
        if (b >= a.Np) return;
        int e0a = a.off0[b];
        int dega = a.off0[b + 1] - e0a;
        float4 x0, x1;
        warp_rel_agg(a.srcs0, e0a, dega, dega > 0 ? a.sdst0[b] : 0.f, a.ssrc0, a.wx0, lane, x0, x1);
        int e0c = a.off2[b];
        int degc = a.off2[b + 1] - e0c;
        float4 c0, c1;
        warp_rel_agg(a.srcs2, e0c, degc, degc > 0 ? a.sdst2[b] : 0.f, a.ssrc2, a.wx2, lane, c0, c1);

        const float4* q4 = (const float4*)a.q + lane * 2;
        float4 q0 = __ldg(q4), q1 = __ldg(q4 + 1);
        float t1 = tanhf(x0.x) * q0.x + tanhf(x0.y) * q0.y + tanhf(x0.z) * q0.z + tanhf(x0.w) * q0.w
                 + tanhf(x1.x) * q1.x + tanhf(x1.y) * q1.y + tanhf(x1.z) * q1.z + tanhf(x1.w) * q1.w;
        float t2 = tanhf(c0.x) * q0.x + tanhf(c0.y) * q0.y + tanhf(c0.z) * q0.z + tanhf(c0.w) * q0.w
                 + tanhf(c1.x) * q1.x + tanhf(c1.y) * q1.y + tanhf(c1.z) * q1.z + tanhf(c1.w) * q1.w;
#pragma unroll
        for (int o = 16; o; o >>= 1) {
            t1 += __shfl_xor_sync(0xffffffffu, t1, o);
            t2 += __shfl_xor_sync(0xffffffffu, t2, o);
        }
        float mm = fmaxf(t1, t2);
        float w1 = expf(t1 - mm), w2 = expf(t2 - mm);
        float z = 1.f / (w1 + w2);
        w1 *= z; w2 *= z;
        float4 s0, s1;
        load_half8(a.selfp, b, lane, s0, s1);
        float v;
        v = s0.x + w1 * x0.x + w2 * c0.x; s0.x = v > 0.f ? v : expm1f(v);
        v = s0.y + w1 * x0.y + w2 * c0.y; s0.y = v > 0.f ? v : expm1f(v);
        v = s0.z + w1 * x0.z + w2 * c0.z; s0.z = v > 0.f ? v : expm1f(v);
        v = s0.w + w1 * x0.w + w2 * c0.w; s0.w = v > 0.f ? v : expm1f(v);
        v = s1.x + w1 * x1.x + w2 * c1.x; s1.x = v > 0.f ? v : expm1f(v);
        v = s1.y + w1 * x1.y + w2 * c1.y; s1.y = v > 0.f ? v : expm1f(v);
        v = s1.z + w1 * x1.z + w2 * c1.z; s1.z = v > 0.f ? v : expm1f(v);
        v = s1.w + w1 * x1.w + w2 * c1.w; s1.w = v > 0.f ? v : expm1f(v);
        float4* o = (float4*)(a.out + (size_t)(a.Na + b) * D) + lane * 2;
        o[0] = s0; o[1] = s1;
    }
}

// ==================== host launch ====================
extern "C" void kernel_launch(void* const* d_in, const int* in_sizes, int n_in,
                              void* d_out, int out_size) {
    const float* h_author = (const float*)d_in[0];
    const float* h_paper  = (const float*)d_in[1];
    const int* ei_ap = (const int*)d_in[2];
    const int* ei_pa = (const int*)d_in[3];
    const int* ei_pp = (const int*)d_in[4];
    const float* W_ap = (const float*)d_in[5];
    const float* a_src_ap = (const float*)d_in[6];
    const float* a_dst_ap = (const float*)d_in[7];
    const float* W_pa = (const float*)d_in[8];
    const float* a_src_pa = (const float*)d_in[9];
    const float* a_dst_pa = (const float*)d_in[10];
    const float* W_pp = (const float*)d_in[11];
    const float* a_src_pp = (const float*)d_in[12];
    const float* a_dst_pp = (const float*)d_in[13];
    const float* Wself_a = (const float*)d_in[14];
    const float* bself_a = (const float*)d_in[15];
    const float* Wself_p = (const float*)d_in[16];
    const float* bself_p = (const float*)d_in[17];
    const float* q_paper  = (const float*)d_in[19];

    int Na = in_sizes[0] / D;
    int Np = in_sizes[1] / D;
    int Eap = in_sizes[2] / 2;
    int Epa = in_sizes[3] / 2;
    int Epp = in_sizes[4] / 2;

    float *wx, *svec, *vv;
    int *cnt, *off, *cur, *srcs, *bsums;
    __nv_bfloat16 *ha, *hp, *wsp;
    cudaGetSymbolAddress((void**)&wx, g_wx);
    cudaGetSymbolAddress((void**)&svec, g_s);
    cudaGetSymbolAddress((void**)&vv, g_v);
    cudaGetSymbolAddress((void**)&cnt, g_cnt);
    cudaGetSymbolAddress((void**)&off, g_off);
    cudaGetSymbolAddress((void**)&cur, g_cur);
    cudaGetSymbolAddress((void**)&srcs, g_srcs);
    cudaGetSymbolAddress((void**)&bsums, g_bsums);
    cudaGetSymbolAddress((void**)&ha, g_ha);
    cudaGetSymbolAddress((void**)&hp, g_hp);
    cudaGetSymbolAddress((void**)&wsp, g_wsplit);

    const size_t WXS = (size_t)NMAX * D;
    float* wxp[7];
    for (int i = 0; i < 7; i++) wxp[i] = wx + i * WXS;
    __half* hx0 = (__half*)wxp[0];
    __half* hx1 = (__half*)wxp[2];
    __half* hx2 = (__half*)wxp[4];
    __half* hselfA = (__half*)wxp[5];
    __half* hselfP = (__half*)wxp[6];
    float* sp[6];
    for (int i = 0; i < 6; i++) sp[i] = svec + (size_t)i * NMAX;
    __nv_bfloat16* haHi = ha;            __nv_bfloat16* haLo = ha + WXS;
    __nv_bfloat16* hpHi = hp;            __nv_bfloat16* hpLo = hp + WXS;
    __nv_bfloat16* wHi[5]; __nv_bfloat16* wLo[5];
    for (int i = 0; i < 5; i++) { wHi[i] = wsp + (size_t)(2 * i) * D * D; wLo[i] = wHi[i] + D * D; }

    // (1) split + zero
    SplitZeroArgs sz;
    sz.j[0] = {h_author, haHi, haLo, Na * D};
    sz.j[1] = {h_paper,  hpHi, hpLo, Np * D};
    sz.j[2] = {W_ap,    wHi[0], wLo[0], D * D};
    sz.j[3] = {W_pa,    wHi[1], wLo[1], D * D};
    sz.j[4] = {W_pp,    wHi[2], wLo[2], D * D};
    sz.j[5] = {Wself_a, wHi[3], wLo[3], D * D};
    sz.j[6] = {Wself_p, wHi[4], wLo[4], D * D};
    sz.cnt = cnt; sz.svec = svec;
    split_zero<<<dim3(148, 8), 256>>>(sz);

    // (2) histogram   (3) scanA
    int Emax3 = max(Eap, max(Epa, Epp));
    hist3_kernel<<<dim3((Emax3 + 255) / 256, 3), 256>>>(ei_ap, ei_pa, ei_pp, Eap, Epa, Epp, cnt);
    scanA_kernel<<<dim3(49, 3), 1024>>>(cnt, off, bsums, Np, Na, Np);

    // (4) batched HMMA GEMMs  [4th launch -> ncu window]
    GemmJobs gj;
    gj.j[0] = {haHi, haLo, wHi[0], wLo[0], hx0, nullptr, a_src_ap, sp[0], nullptr, nullptr, Na, 0};
    gj.j[1] = {hpHi, hpLo, wHi[1], wLo[1], hx1, nullptr, a_src_pa, sp[2], nullptr, nullptr, Np, 0};
    gj.j[2] = {hpHi, hpLo, wHi[2], wLo[2], hx2, nullptr, a_src_pp, sp[4], a_dst_pp, sp[5], Np, 0};
    gj.j[3] = {haHi, haLo, wHi[3], wLo[3], hselfA, bself_a, nullptr, nullptr, nullptr, nullptr, Na, 0};
    gj.j[4] = {hpHi, hpLo, wHi[4], wLo[4], hselfP, bself_p, nullptr, nullptr, nullptr, nullptr, Np, 0};
    int maxM = max(Na, Np);
    cudaFuncSetAttribute(gemm_batch, cudaFuncAttributeMaxDynamicSharedMemorySize, GSM_BYTES);
    gemm_batch<<<dim3((maxM + 127) / 128, 2, 5), 256, GSM_BYTES>>>(gj);

    // (5) scanB + matvec (merged)   (6) scanC
    scanB_matvec<<<5, 256>>>(bsums, off, Np, Na, Np, W_ap, a_dst_ap, W_pa, a_dst_pa, vv);
    scanC_kernel<<<dim3(49, 3), 1024>>>(bsums, off, cur, Np, Na, Np);

    // (7) scatter + dotv (merged)
    int sx = max((Emax3 + 255) / 256, (maxM + 7) / 8);
    scatter_dotv<<<dim3(sx, 5), 256>>>(ei_ap, ei_pa, ei_pp, Eap, Epa, Epp, cur, srcs,
                                       h_paper, h_author, vv, sp[1], sp[3], Np, Na);

    // (8) combined aggregation -> output
    float* out = (float*)d_out;
    AggArgs aa;
    aa.srcs0 = srcs + 0 * EMAX; aa.off0 = off + 0 * (NMAX + 1);
    aa.ssrc0 = sp[0]; aa.sdst0 = sp[1]; aa.wx0 = hx0;
    aa.srcs1 = srcs + 1 * EMAX; aa.off1 = off + 1 * (NMAX + 1);
    aa.ssrc1 = sp[2]; aa.sdst1 = sp[3]; aa.wx1 = hx1;
    aa.srcs2 = srcs + 2 * EMAX; aa.off2 = off + 2 * (NMAX + 1);
    aa.ssrc2 = sp[4]; aa.sdst2 = sp[5]; aa.wx2 = hx2;
    aa.selfa = hselfA; aa.selfp = hselfP; aa.q = q_paper;
    aa.out = out; aa.Na = Na; aa.Np = Np;
    aa.nblocksA = (Na + 7) / 8;
    int nblocksP = (Np + 7) / 8;
    agg_all<<<aa.nblocksA + nblocksP, 256>>>(aa);
}